// round 2
// baseline (speedup 1.0000x reference)
#include <cuda_runtime.h>
#include <cuda_bf16.h>
#include <math.h>

// Problem constants (fixed shapes)
#define NN 10000
#define EE 640000
#define FH 128          // F_IN == H == 128
#define CC 40

// ---------------- scratch (device globals; no allocation allowed) ----------------
__device__ __align__(256) int   g_cnt[NN];          // in-degree counts (no self-loop)
__device__ __align__(256) int   g_rowptr[NN + 1];   // CSR row pointers (by dst)
__device__ __align__(256) int   g_cursor[NN];       // fill cursors
__device__ __align__(256) float g_dinv[NN];         // rsqrt(deg) with self-loop
__device__ __align__(256) int   g_csrc[EE];         // CSR src indices
__device__ __align__(256) float g_h[NN * FH];       // GEMM output buffer
__device__ __align__(256) float g_ha[NN * FH];      // aggregation output buffer
__device__ int g_is64;                               // 1 if edge_index is int64

// ---------------- kernel A: detect edge_index dtype ----------------
// Safe under both dtypes: reads only the first 16 32-bit words (buffer holds
// at least 2E*4 bytes). For int64 data the odd words (high halves) are all 0;
// for int32 data they are random node indices (all-zero is ~impossible).
__global__ void k_detect(const int* __restrict__ w) {
    int is64 = 1;
    #pragma unroll
    for (int i = 0; i < 8; i++)
        if (w[2 * i + 1] != 0) is64 = 0;
    g_is64 = is64;
}

__device__ __forceinline__ int load_idx(const void* __restrict__ ei, int is64, long long pos) {
    if (is64) return (int)(((const long long*)ei)[pos]);
    return ((const int*)ei)[pos];
}

// ---------------- kernel 0: zero counts ----------------
__global__ void k_init_cnt() {
    int i = blockIdx.x * blockDim.x + threadIdx.x;
    if (i < NN) g_cnt[i] = 0;
}

// ---------------- kernel 1: histogram of dst ----------------
__global__ void k_count(const void* __restrict__ ei) {
    int e = blockIdx.x * blockDim.x + threadIdx.x;
    int is64 = g_is64;
    if (e < EE) {
        int dst = load_idx(ei, is64, (long long)EE + e);
        if (dst >= 0 && dst < NN) atomicAdd(&g_cnt[dst], 1);
    }
}

// ---------------- kernel 2: single-block exclusive scan + dinv + cursor init ----------------
__global__ void k_scan() {
    __shared__ int wsum[32];
    int t = threadIdx.x;
    int lane = t & 31, wid = t >> 5;
    int carry = 0;
    for (int base = 0; base < NN + 1023; base += 1024) {
        int i = base + t;
        int v = (i < NN) ? g_cnt[i] : 0;
        // warp inclusive scan
        int x = v;
        #pragma unroll
        for (int o = 1; o < 32; o <<= 1) {
            int y = __shfl_up_sync(0xFFFFFFFFu, x, o);
            if (lane >= o) x += y;
        }
        if (lane == 31) wsum[wid] = x;
        __syncthreads();
        if (wid == 0) {
            int s = wsum[lane];
            #pragma unroll
            for (int o = 1; o < 32; o <<= 1) {
                int y = __shfl_up_sync(0xFFFFFFFFu, s, o);
                if (lane >= o) s += y;
            }
            wsum[lane] = s;
        }
        __syncthreads();
        int woff = (wid > 0) ? wsum[wid - 1] : 0;
        int incl = x + woff;
        if (i < NN) {
            g_rowptr[i] = carry + incl - v;   // exclusive prefix
            g_dinv[i]   = rsqrtf((float)(v + 1));
            g_cursor[i] = 0;
        }
        int btot = wsum[31];
        __syncthreads();
        carry += btot;
        if (base >= NN) break;
    }
    if (t == 0) g_rowptr[NN] = carry;
}

// ---------------- kernel 3: fill CSR ----------------
__global__ void k_fill(const void* __restrict__ ei) {
    int e = blockIdx.x * blockDim.x + threadIdx.x;
    int is64 = g_is64;
    if (e < EE) {
        int src = load_idx(ei, is64, e);
        int dst = load_idx(ei, is64, (long long)EE + e);
        if (dst >= 0 && dst < NN && src >= 0 && src < NN) {
            int pos = atomicAdd(&g_cursor[dst], 1);
            g_csrc[g_rowptr[dst] + pos] = src;
        }
    }
}

// ---------------- GEMM: C[M,128] = A[M,128] @ W[128,128] ----------------
// BM=64, BN=128, BK=32, 256 threads, 4x8 per thread
__global__ void k_gemm(const float* __restrict__ A, const float* __restrict__ W,
                       float* __restrict__ Cmat) {
    __shared__ float As[64][32];
    __shared__ float Bs[32][128];
    int tid = threadIdx.x;
    int tx = tid & 15;          // 0..15 -> 8 cols each
    int ty = tid >> 4;          // 0..15 -> 4 rows each
    int rowBase = blockIdx.x * 64;

    float acc[4][8];
    #pragma unroll
    for (int j = 0; j < 4; j++)
        #pragma unroll
        for (int i = 0; i < 8; i++) acc[j][i] = 0.0f;

    for (int k0 = 0; k0 < 128; k0 += 32) {
        // load A tile: 64x32 floats = 512 float4, 2 per thread
        #pragma unroll
        for (int p = 0; p < 2; p++) {
            int f = tid + p * 256;
            int r = f >> 3, c4 = f & 7;
            int grow = rowBase + r;
            float4 v = make_float4(0.f, 0.f, 0.f, 0.f);
            if (grow < NN)
                v = *(const float4*)&A[grow * 128 + k0 + c4 * 4];
            *(float4*)&As[r][c4 * 4] = v;
        }
        // load B tile: 32x128 floats = 1024 float4, 4 per thread
        #pragma unroll
        for (int p = 0; p < 4; p++) {
            int f = tid + p * 256;
            int r = f >> 5, c4 = f & 31;
            float4 v = *(const float4*)&W[(k0 + r) * 128 + c4 * 4];
            *(float4*)&Bs[r][c4 * 4] = v;
        }
        __syncthreads();
        #pragma unroll
        for (int kk = 0; kk < 32; kk++) {
            float a[4];
            #pragma unroll
            for (int j = 0; j < 4; j++) a[j] = As[ty * 4 + j][kk];
            float4 b0 = *(float4*)&Bs[kk][tx * 8];
            float4 b1 = *(float4*)&Bs[kk][tx * 8 + 4];
            float b[8] = {b0.x, b0.y, b0.z, b0.w, b1.x, b1.y, b1.z, b1.w};
            #pragma unroll
            for (int j = 0; j < 4; j++)
                #pragma unroll
                for (int i = 0; i < 8; i++)
                    acc[j][i] = fmaf(a[j], b[i], acc[j][i]);
        }
        __syncthreads();
    }

    #pragma unroll
    for (int j = 0; j < 4; j++) {
        int row = rowBase + ty * 4 + j;
        if (row < NN) {
            float4 o0 = make_float4(acc[j][0], acc[j][1], acc[j][2], acc[j][3]);
            float4 o1 = make_float4(acc[j][4], acc[j][5], acc[j][6], acc[j][7]);
            *(float4*)&Cmat[row * 128 + tx * 8]     = o0;
            *(float4*)&Cmat[row * 128 + tx * 8 + 4] = o1;
        }
    }
}

// ---------------- aggregation: one warp per node, CSR gather ----------------
__global__ void k_agg(const float* __restrict__ h, const float* __restrict__ bias,
                      float* __restrict__ out, int doRelu) {
    int warp = blockIdx.x * (blockDim.x >> 5) + (threadIdx.x >> 5);
    if (warp >= NN) return;
    int lane = threadIdx.x & 31;
    const float4* __restrict__ h4 = (const float4*)h;

    float di = g_dinv[warp];
    float w0 = di * di;
    float4 sv = h4[warp * 32 + lane];              // self-loop message
    float4 acc = make_float4(sv.x * w0, sv.y * w0, sv.z * w0, sv.w * w0);

    int e   = g_rowptr[warp];
    int end = g_rowptr[warp + 1];

    // 4-way unroll for MLP
    for (; e + 4 <= end; e += 4) {
        int s0 = g_csrc[e + 0];
        int s1 = g_csrc[e + 1];
        int s2 = g_csrc[e + 2];
        int s3 = g_csrc[e + 3];
        float w_0 = g_dinv[s0] * di;
        float w_1 = g_dinv[s1] * di;
        float w_2 = g_dinv[s2] * di;
        float w_3 = g_dinv[s3] * di;
        float4 v0 = h4[s0 * 32 + lane];
        float4 v1 = h4[s1 * 32 + lane];
        float4 v2 = h4[s2 * 32 + lane];
        float4 v3 = h4[s3 * 32 + lane];
        acc.x = fmaf(v0.x, w_0, acc.x); acc.y = fmaf(v0.y, w_0, acc.y);
        acc.z = fmaf(v0.z, w_0, acc.z); acc.w = fmaf(v0.w, w_0, acc.w);
        acc.x = fmaf(v1.x, w_1, acc.x); acc.y = fmaf(v1.y, w_1, acc.y);
        acc.z = fmaf(v1.z, w_1, acc.z); acc.w = fmaf(v1.w, w_1, acc.w);
        acc.x = fmaf(v2.x, w_2, acc.x); acc.y = fmaf(v2.y, w_2, acc.y);
        acc.z = fmaf(v2.z, w_2, acc.z); acc.w = fmaf(v2.w, w_2, acc.w);
        acc.x = fmaf(v3.x, w_3, acc.x); acc.y = fmaf(v3.y, w_3, acc.y);
        acc.z = fmaf(v3.z, w_3, acc.z); acc.w = fmaf(v3.w, w_3, acc.w);
    }
    for (; e < end; e++) {
        int s = g_csrc[e];
        float w = g_dinv[s] * di;
        float4 v = h4[s * 32 + lane];
        acc.x = fmaf(v.x, w, acc.x); acc.y = fmaf(v.y, w, acc.y);
        acc.z = fmaf(v.z, w, acc.z); acc.w = fmaf(v.w, w, acc.w);
    }

    float4 b = ((const float4*)bias)[lane];
    acc.x += b.x; acc.y += b.y; acc.z += b.z; acc.w += b.w;
    if (doRelu) {
        acc.x = fmaxf(acc.x, 0.f); acc.y = fmaxf(acc.y, 0.f);
        acc.z = fmaxf(acc.z, 0.f); acc.w = fmaxf(acc.w, 0.f);
    }
    ((float4*)out)[warp * 32 + lane] = acc;
}

// ---------------- head: logits = h @ Wc + bc; log_softmax ----------------
// blockDim (40, 8): 8 rows per block
__global__ void k_head(const float* __restrict__ h, const float* __restrict__ Wc,
                       const float* __restrict__ bc, float* __restrict__ out) {
    __shared__ float Wcs[128 * CC];
    __shared__ float bcs[CC];
    __shared__ float hs[8][128];
    __shared__ float lg[8][CC];
    __shared__ float lse_s[8];

    int tx = threadIdx.x, ty = threadIdx.y;
    int tid = ty * CC + tx;
    for (int i = tid; i < 128 * CC; i += CC * 8) Wcs[i] = Wc[i];
    if (tid < CC) bcs[tid] = bc[tid];

    int row = blockIdx.x * 8 + ty;
    if (row < NN)
        for (int k = tx; k < 128; k += CC) hs[ty][k] = h[row * 128 + k];
    __syncthreads();

    if (row < NN) {
        float acc = 0.0f;
        #pragma unroll 16
        for (int k = 0; k < 128; k++)
            acc = fmaf(hs[ty][k], Wcs[k * CC + tx], acc);
        lg[ty][tx] = acc + bcs[tx];
    }
    __syncthreads();
    if (tx == 0 && row < NN) {
        float m = -1e30f;
        #pragma unroll
        for (int c = 0; c < CC; c++) m = fmaxf(m, lg[ty][c]);
        float s = 0.0f;
        #pragma unroll
        for (int c = 0; c < CC; c++) s += expf(lg[ty][c] - m);
        lse_s[ty] = m + logf(s);
    }
    __syncthreads();
    if (row < NN)
        out[row * CC + tx] = lg[ty][tx] - lse_s[ty];
}

// ---------------- launch ----------------
extern "C" void kernel_launch(void* const* d_in, const int* in_sizes, int n_in,
                              void* d_out, int out_size) {
    const float* x   = (const float*)d_in[0];
    const void*  ei  = d_in[1];
    const float* W1  = (const float*)d_in[2];
    const float* b1  = (const float*)d_in[3];
    const float* W2  = (const float*)d_in[4];
    const float* b2  = (const float*)d_in[5];
    const float* Wc  = (const float*)d_in[6];
    const float* bc  = (const float*)d_in[7];
    float* out = (float*)d_out;

    float* d_h;  cudaGetSymbolAddress((void**)&d_h,  g_h);
    float* d_ha; cudaGetSymbolAddress((void**)&d_ha, g_ha);

    // CSR build (per launch; deterministic work)
    k_detect<<<1, 1>>>((const int*)ei);
    k_init_cnt<<<(NN + 255) / 256, 256>>>();
    k_count<<<(EE + 255) / 256, 256>>>(ei);
    k_scan<<<1, 1024>>>();
    k_fill<<<(EE + 255) / 256, 256>>>(ei);

    int gemm_grid = (NN + 63) / 64;
    int agg_grid  = (NN + 7) / 8;

    // layer 1
    k_gemm<<<gemm_grid, 256>>>(x, W1, d_h);
    k_agg<<<agg_grid, 256>>>(d_h, b1, d_ha, 1);
    // layer 2
    k_gemm<<<gemm_grid, 256>>>(d_ha, W2, d_h);
    k_agg<<<agg_grid, 256>>>(d_h, b2, d_ha, 0);
    // head + log-softmax
    dim3 hb(CC, 8);
    k_head<<<(NN + 7) / 8, hb>>>(d_ha, Wc, bc, out);
}

// round 3
// speedup vs baseline: 1.3248x; 1.3248x over previous
#include <cuda_runtime.h>
#include <cuda_bf16.h>
#include <math.h>

// Problem constants (fixed shapes)
#define NN 10000
#define EE 640000
#define FH 128          // F_IN == H == 128
#define CC 40
#define BKT 256         // bucket capacity per node (max degree ~100 for this dist)

// ---------------- scratch (device globals; no allocation allowed) ----------------
__device__ __align__(256) int   g_cnt[NN];          // in-degree counts (no self-loop)
__device__ __align__(256) float g_dinv[NN];         // rsqrt(deg) with self-loop
__device__ __align__(256) int   g_bkt[NN * BKT];    // padded adjacency buckets (src ids)
__device__ __align__(256) float g_h[NN * FH];       // GEMM output buffer
__device__ __align__(256) float g_ha[NN * FH];      // aggregation output buffer
__device__ int g_is64;                               // 1 if edge_index is int64

// ---------------- kernel 0: zero counts + detect edge dtype ----------------
// For int64 data the high 32-bit words of the first 8 indices are all zero;
// for int32 random node ids that is essentially impossible.
__global__ void k_init(const int* __restrict__ w) {
    int i = blockIdx.x * blockDim.x + threadIdx.x;
    if (i < NN) g_cnt[i] = 0;
    if (i == 0) {
        int is64 = 1;
        #pragma unroll
        for (int j = 0; j < 8; j++)
            if (w[2 * j + 1] != 0) is64 = 0;
        g_is64 = is64;
    }
}

__device__ __forceinline__ int load_idx(const void* __restrict__ ei, int is64, long long pos) {
    if (is64) return (int)(((const long long*)ei)[pos]);
    return ((const int*)ei)[pos];
}

// ---------------- kernel 1: single-pass bucket build ----------------
__global__ void k_build(const void* __restrict__ ei) {
    int e = blockIdx.x * blockDim.x + threadIdx.x;
    int is64 = g_is64;
    if (e < EE) {
        int src = load_idx(ei, is64, e);
        int dst = load_idx(ei, is64, (long long)EE + e);
        if ((unsigned)dst < NN && (unsigned)src < NN) {
            int pos = atomicAdd(&g_cnt[dst], 1);
            if (pos < BKT) g_bkt[dst * BKT + pos] = src;
        }
    }
}

// ---------------- kernel 2: dinv from final counts ----------------
__global__ void k_deg() {
    int i = blockIdx.x * blockDim.x + threadIdx.x;
    if (i < NN) g_dinv[i] = rsqrtf((float)(g_cnt[i] + 1));
}

// ---------------- GEMM: C[M,128] = A[M,128] @ W[128,128] ----------------
// BM=64, BN=128, BK=32, 256 threads, 4x8 per thread
__global__ void k_gemm(const float* __restrict__ A, const float* __restrict__ W,
                       float* __restrict__ Cmat) {
    __shared__ float As[64][32];
    __shared__ float Bs[32][128];
    int tid = threadIdx.x;
    int tx = tid & 15;          // 0..15 -> 8 cols each
    int ty = tid >> 4;          // 0..15 -> 4 rows each
    int rowBase = blockIdx.x * 64;

    float acc[4][8];
    #pragma unroll
    for (int j = 0; j < 4; j++)
        #pragma unroll
        for (int i = 0; i < 8; i++) acc[j][i] = 0.0f;

    for (int k0 = 0; k0 < 128; k0 += 32) {
        #pragma unroll
        for (int p = 0; p < 2; p++) {
            int f = tid + p * 256;
            int r = f >> 3, c4 = f & 7;
            int grow = rowBase + r;
            float4 v = make_float4(0.f, 0.f, 0.f, 0.f);
            if (grow < NN)
                v = *(const float4*)&A[grow * 128 + k0 + c4 * 4];
            *(float4*)&As[r][c4 * 4] = v;
        }
        #pragma unroll
        for (int p = 0; p < 4; p++) {
            int f = tid + p * 256;
            int r = f >> 5, c4 = f & 31;
            float4 v = *(const float4*)&W[(k0 + r) * 128 + c4 * 4];
            *(float4*)&Bs[r][c4 * 4] = v;
        }
        __syncthreads();
        #pragma unroll
        for (int kk = 0; kk < 32; kk++) {
            float a[4];
            #pragma unroll
            for (int j = 0; j < 4; j++) a[j] = As[ty * 4 + j][kk];
            float4 b0 = *(float4*)&Bs[kk][tx * 8];
            float4 b1 = *(float4*)&Bs[kk][tx * 8 + 4];
            float b[8] = {b0.x, b0.y, b0.z, b0.w, b1.x, b1.y, b1.z, b1.w};
            #pragma unroll
            for (int j = 0; j < 4; j++)
                #pragma unroll
                for (int i = 0; i < 8; i++)
                    acc[j][i] = fmaf(a[j], b[i], acc[j][i]);
        }
        __syncthreads();
    }

    #pragma unroll
    for (int j = 0; j < 4; j++) {
        int row = rowBase + ty * 4 + j;
        if (row < NN) {
            float4 o0 = make_float4(acc[j][0], acc[j][1], acc[j][2], acc[j][3]);
            float4 o1 = make_float4(acc[j][4], acc[j][5], acc[j][6], acc[j][7]);
            *(float4*)&Cmat[row * 128 + tx * 8]     = o0;
            *(float4*)&Cmat[row * 128 + tx * 8 + 4] = o1;
        }
    }
}

// ---------------- helper: warp gather-accumulate for one node ----------------
__device__ __forceinline__ float4 gather_node(const float4* __restrict__ h4,
                                              int node, int lane) {
    float di = g_dinv[node];
    float w0 = di * di;
    float4 sv = h4[node * 32 + lane];              // self-loop message
    float4 acc = make_float4(sv.x * w0, sv.y * w0, sv.z * w0, sv.w * w0);

    int n = g_cnt[node];
    if (n > BKT) n = BKT;
    const int* __restrict__ bp = &g_bkt[node * BKT];
    int e = 0;
    for (; e + 4 <= n; e += 4) {
        int s0 = bp[e + 0], s1 = bp[e + 1], s2 = bp[e + 2], s3 = bp[e + 3];
        float w_0 = g_dinv[s0] * di;
        float w_1 = g_dinv[s1] * di;
        float w_2 = g_dinv[s2] * di;
        float w_3 = g_dinv[s3] * di;
        float4 v0 = h4[s0 * 32 + lane];
        float4 v1 = h4[s1 * 32 + lane];
        float4 v2 = h4[s2 * 32 + lane];
        float4 v3 = h4[s3 * 32 + lane];
        acc.x = fmaf(v0.x, w_0, acc.x); acc.y = fmaf(v0.y, w_0, acc.y);
        acc.z = fmaf(v0.z, w_0, acc.z); acc.w = fmaf(v0.w, w_0, acc.w);
        acc.x = fmaf(v1.x, w_1, acc.x); acc.y = fmaf(v1.y, w_1, acc.y);
        acc.z = fmaf(v1.z, w_1, acc.z); acc.w = fmaf(v1.w, w_1, acc.w);
        acc.x = fmaf(v2.x, w_2, acc.x); acc.y = fmaf(v2.y, w_2, acc.y);
        acc.z = fmaf(v2.z, w_2, acc.z); acc.w = fmaf(v2.w, w_2, acc.w);
        acc.x = fmaf(v3.x, w_3, acc.x); acc.y = fmaf(v3.y, w_3, acc.y);
        acc.z = fmaf(v3.z, w_3, acc.z); acc.w = fmaf(v3.w, w_3, acc.w);
    }
    for (; e < n; e++) {
        int s = bp[e];
        float w = g_dinv[s] * di;
        float4 v = h4[s * 32 + lane];
        acc.x = fmaf(v.x, w, acc.x); acc.y = fmaf(v.y, w, acc.y);
        acc.z = fmaf(v.z, w, acc.z); acc.w = fmaf(v.w, w, acc.w);
    }
    return acc;
}

// ---------------- layer-1 aggregation: warp per node, +b1, relu ----------------
__global__ void k_agg1(const float* __restrict__ h, const float* __restrict__ bias,
                       float* __restrict__ out) {
    int node = blockIdx.x * (blockDim.x >> 5) + (threadIdx.x >> 5);
    if (node >= NN) return;
    int lane = threadIdx.x & 31;
    float4 acc = gather_node((const float4*)h, node, lane);
    float4 b = ((const float4*)bias)[lane];
    acc.x = fmaxf(acc.x + b.x, 0.f);
    acc.y = fmaxf(acc.y + b.y, 0.f);
    acc.z = fmaxf(acc.z + b.z, 0.f);
    acc.w = fmaxf(acc.w + b.w, 0.f);
    ((float4*)out)[node * 32 + lane] = acc;
}

// ---------------- layer-2 aggregation fused with head + log-softmax ----------------
// 256 threads = 8 warps = 8 nodes per block. Wc staged in smem.
__global__ void k_agg2_head(const float* __restrict__ h, const float* __restrict__ b2,
                            const float* __restrict__ Wc, const float* __restrict__ bc,
                            float* __restrict__ out) {
    __shared__ float Wcs[FH * CC];     // 20 KB
    __shared__ float bcs[CC];
    __shared__ float hrow[8][FH];

    int tid = threadIdx.x;
    int lane = tid & 31;
    int w = tid >> 5;
    for (int i = tid; i < FH * CC; i += 256) Wcs[i] = Wc[i];
    if (tid < CC) bcs[tid] = bc[tid];
    __syncthreads();

    int node = blockIdx.x * 8 + w;
    if (node >= NN) return;

    float4 acc = gather_node((const float4*)h, node, lane);
    float4 b = ((const float4*)b2)[lane];
    acc.x += b.x; acc.y += b.y; acc.z += b.z; acc.w += b.w;

    *(float4*)&hrow[w][lane * 4] = acc;
    __syncwarp();

    // logits: 2 classes per lane (c0 = lane, c1 = 32 + lane for lane < 8)
    int c0 = lane;
    int c1 = 32 + lane;
    float l0 = bcs[c0];
    float l1 = (c1 < CC) ? bcs[c1] : -1e30f;
    #pragma unroll 8
    for (int k = 0; k < FH; k++) {
        float hv = hrow[w][k];
        l0 = fmaf(hv, Wcs[k * CC + c0], l0);
        if (c1 < CC) l1 = fmaf(hv, Wcs[k * CC + c1], l1);
    }

    // warp-wide log-softmax over 40 values
    float m = fmaxf(l0, l1);
    #pragma unroll
    for (int o = 16; o > 0; o >>= 1)
        m = fmaxf(m, __shfl_xor_sync(0xFFFFFFFFu, m, o));
    float s = __expf(l0 - m) + ((c1 < CC) ? __expf(l1 - m) : 0.0f);
    #pragma unroll
    for (int o = 16; o > 0; o >>= 1)
        s += __shfl_xor_sync(0xFFFFFFFFu, s, o);
    float lse = m + __logf(s);

    out[node * CC + c0] = l0 - lse;
    if (c1 < CC) out[node * CC + c1] = l1 - lse;
}

// ---------------- launch ----------------
extern "C" void kernel_launch(void* const* d_in, const int* in_sizes, int n_in,
                              void* d_out, int out_size) {
    const float* x   = (const float*)d_in[0];
    const void*  ei  = d_in[1];
    const float* W1  = (const float*)d_in[2];
    const float* b1  = (const float*)d_in[3];
    const float* W2  = (const float*)d_in[4];
    const float* b2  = (const float*)d_in[5];
    const float* Wc  = (const float*)d_in[6];
    const float* bc  = (const float*)d_in[7];
    float* out = (float*)d_out;

    float* d_h;  cudaGetSymbolAddress((void**)&d_h,  g_h);
    float* d_ha; cudaGetSymbolAddress((void**)&d_ha, g_ha);

    static cudaStream_t s2 = nullptr;
    static cudaEvent_t evFork = nullptr, evJoin = nullptr;
    if (!s2) {
        cudaStreamCreateWithFlags(&s2, cudaStreamNonBlocking);
        cudaEventCreateWithFlags(&evFork, cudaEventDisableTiming);
        cudaEventCreateWithFlags(&evJoin, cudaEventDisableTiming);
    }

    int gemm_grid = (NN + 63) / 64;
    int agg_grid  = (NN + 7) / 8;

    // fork: GEMM1 (x @ W1) is independent of the edge structure
    cudaEventRecord(evFork, 0);
    cudaStreamWaitEvent(s2, evFork, 0);
    k_gemm<<<gemm_grid, 256, 0, s2>>>(x, W1, d_h);
    cudaEventRecord(evJoin, s2);

    // bucket build on main stream (concurrent with GEMM1)
    k_init<<<(NN + 255) / 256, 256>>>((const int*)ei);
    k_build<<<(EE + 255) / 256, 256>>>(ei);
    k_deg<<<(NN + 255) / 256, 256>>>();

    // join before aggregation needs d_h
    cudaStreamWaitEvent(0, evJoin, 0);

    // layer 1 aggregate (+b1, relu)
    k_agg1<<<agg_grid, 256>>>(d_h, b1, d_ha);
    // layer 2 GEMM
    k_gemm<<<gemm_grid, 256>>>(d_ha, W2, d_h);
    // layer 2 aggregate + head + log-softmax
    k_agg2_head<<<agg_grid, 256>>>(d_h, b2, Wc, bc, out);
}

// round 4
// speedup vs baseline: 1.3589x; 1.0258x over previous
#include <cuda_runtime.h>
#include <cuda_bf16.h>
#include <math.h>

// Problem constants (fixed shapes)
#define NN 10000
#define EE 640000
#define FH 128          // F_IN == H == 128
#define CC 40
#define BKT 256         // bucket capacity per node (max degree ~100 for this dist)

// ---------------- scratch (device globals; no allocation allowed) ----------------
__device__ __align__(256) int   g_cnt[NN];          // in-degree counts (no self-loop)
__device__ __align__(256) int   g_bkt[NN * BKT];    // padded adjacency buckets (src ids)
__device__ __align__(256) float g_h[NN * FH];       // GEMM1 output buffer
__device__ __align__(256) float g_ha[NN * FH];      // layer-1 output (relu'd)
__device__ __align__(256) float g_wf[FH * CC];      // Wfused = W2 @ Wc
__device__ __align__(256) float g_bf[CC];           // bfused = b2 @ Wc + bc
__device__ int g_is64;                               // 1 if edge_index is int64

// ---------------- kernel 0: zero counts + detect edge dtype ----------------
// For int64 data the high 32-bit words of the first 8 indices are all zero;
// for int32 random node ids that is essentially impossible.
__global__ void k_init(const int* __restrict__ w) {
    int i = blockIdx.x * blockDim.x + threadIdx.x;
    if (i < NN) g_cnt[i] = 0;
    if (i == 0) {
        int is64 = 1;
        #pragma unroll
        for (int j = 0; j < 8; j++)
            if (w[2 * j + 1] != 0) is64 = 0;
        g_is64 = is64;
    }
}

__device__ __forceinline__ int load_idx(const void* __restrict__ ei, int is64, long long pos) {
    if (is64) return (int)(((const long long*)ei)[pos]);
    return ((const int*)ei)[pos];
}

// ---------------- kernel 1: single-pass bucket build ----------------
__global__ void k_build(const void* __restrict__ ei) {
    int e = blockIdx.x * blockDim.x + threadIdx.x;
    int is64 = g_is64;
    if (e < EE) {
        int src = load_idx(ei, is64, e);
        int dst = load_idx(ei, is64, (long long)EE + e);
        if ((unsigned)dst < NN && (unsigned)src < NN) {
            int pos = atomicAdd(&g_cnt[dst], 1);
            if (pos < BKT) g_bkt[dst * BKT + pos] = src;
        }
    }
}

// ---------------- kernel: Wfused = W2 @ Wc, bfused = b2 @ Wc + bc ----------------
// 5120 outputs, one thread each. grid 10 x 512.
__global__ void k_fusew(const float* __restrict__ W2, const float* __restrict__ Wc,
                        const float* __restrict__ b2, const float* __restrict__ bc) {
    int idx = blockIdx.x * blockDim.x + threadIdx.x;
    if (idx < FH * CC) {
        int k = idx / CC;       // row of W2
        int c = idx % CC;       // col of Wc
        float acc = 0.0f;
        #pragma unroll 8
        for (int j = 0; j < FH; j++)
            acc = fmaf(W2[k * FH + j], Wc[j * CC + c], acc);
        g_wf[idx] = acc;
    }
    if (idx < CC) {
        float acc = bc[idx];
        #pragma unroll 8
        for (int j = 0; j < FH; j++)
            acc = fmaf(b2[j], Wc[j * CC + idx], acc);
        g_bf[idx] = acc;
    }
}

// ---------------- GEMM: C[M,128] = A[M,128] @ W[128,128] ----------------
// BM=64, BN=128, BK=32, 256 threads, 4x8 per thread
__global__ void k_gemm(const float* __restrict__ A, const float* __restrict__ W,
                       float* __restrict__ Cmat) {
    __shared__ float As[64][32];
    __shared__ float Bs[32][128];
    int tid = threadIdx.x;
    int tx = tid & 15;          // 0..15 -> 8 cols each
    int ty = tid >> 4;          // 0..15 -> 4 rows each
    int rowBase = blockIdx.x * 64;

    float acc[4][8];
    #pragma unroll
    for (int j = 0; j < 4; j++)
        #pragma unroll
        for (int i = 0; i < 8; i++) acc[j][i] = 0.0f;

    for (int k0 = 0; k0 < 128; k0 += 32) {
        #pragma unroll
        for (int p = 0; p < 2; p++) {
            int f = tid + p * 256;
            int r = f >> 3, c4 = f & 7;
            int grow = rowBase + r;
            float4 v = make_float4(0.f, 0.f, 0.f, 0.f);
            if (grow < NN)
                v = *(const float4*)&A[grow * 128 + k0 + c4 * 4];
            *(float4*)&As[r][c4 * 4] = v;
        }
        #pragma unroll
        for (int p = 0; p < 4; p++) {
            int f = tid + p * 256;
            int r = f >> 5, c4 = f & 31;
            float4 v = *(const float4*)&W[(k0 + r) * 128 + c4 * 4];
            *(float4*)&Bs[r][c4 * 4] = v;
        }
        __syncthreads();
        #pragma unroll
        for (int kk = 0; kk < 32; kk++) {
            float a[4];
            #pragma unroll
            for (int j = 0; j < 4; j++) a[j] = As[ty * 4 + j][kk];
            float4 b0 = *(float4*)&Bs[kk][tx * 8];
            float4 b1 = *(float4*)&Bs[kk][tx * 8 + 4];
            float b[8] = {b0.x, b0.y, b0.z, b0.w, b1.x, b1.y, b1.z, b1.w};
            #pragma unroll
            for (int j = 0; j < 4; j++)
                #pragma unroll
                for (int i = 0; i < 8; i++)
                    acc[j][i] = fmaf(a[j], b[i], acc[j][i]);
        }
        __syncthreads();
    }

    #pragma unroll
    for (int j = 0; j < 4; j++) {
        int row = rowBase + ty * 4 + j;
        if (row < NN) {
            float4 o0 = make_float4(acc[j][0], acc[j][1], acc[j][2], acc[j][3]);
            float4 o1 = make_float4(acc[j][4], acc[j][5], acc[j][6], acc[j][7]);
            *(float4*)&Cmat[row * 128 + tx * 8]     = o0;
            *(float4*)&Cmat[row * 128 + tx * 8 + 4] = o1;
        }
    }
}

// ---------------- helper: warp gather-accumulate for one node ----------------
// dinv computed on the fly from counts: rsqrtf(cnt+1).
__device__ __forceinline__ float node_dinv(int v) {
    return rsqrtf((float)(g_cnt[v] + 1));
}

__device__ __forceinline__ float4 gather_node(const float4* __restrict__ h4,
                                              int node, int lane) {
    float di = node_dinv(node);
    float w0 = di * di;
    float4 sv = h4[node * 32 + lane];              // self-loop message
    float4 acc = make_float4(sv.x * w0, sv.y * w0, sv.z * w0, sv.w * w0);

    int n = g_cnt[node];
    if (n > BKT) n = BKT;
    const int* __restrict__ bp = &g_bkt[node * BKT];
    int e = 0;
    for (; e + 4 <= n; e += 4) {
        int s0 = bp[e + 0], s1 = bp[e + 1], s2 = bp[e + 2], s3 = bp[e + 3];
        float w_0 = node_dinv(s0) * di;
        float w_1 = node_dinv(s1) * di;
        float w_2 = node_dinv(s2) * di;
        float w_3 = node_dinv(s3) * di;
        float4 v0 = h4[s0 * 32 + lane];
        float4 v1 = h4[s1 * 32 + lane];
        float4 v2 = h4[s2 * 32 + lane];
        float4 v3 = h4[s3 * 32 + lane];
        acc.x = fmaf(v0.x, w_0, acc.x); acc.y = fmaf(v0.y, w_0, acc.y);
        acc.z = fmaf(v0.z, w_0, acc.z); acc.w = fmaf(v0.w, w_0, acc.w);
        acc.x = fmaf(v1.x, w_1, acc.x); acc.y = fmaf(v1.y, w_1, acc.y);
        acc.z = fmaf(v1.z, w_1, acc.z); acc.w = fmaf(v1.w, w_1, acc.w);
        acc.x = fmaf(v2.x, w_2, acc.x); acc.y = fmaf(v2.y, w_2, acc.y);
        acc.z = fmaf(v2.z, w_2, acc.z); acc.w = fmaf(v2.w, w_2, acc.w);
        acc.x = fmaf(v3.x, w_3, acc.x); acc.y = fmaf(v3.y, w_3, acc.y);
        acc.z = fmaf(v3.z, w_3, acc.z); acc.w = fmaf(v3.w, w_3, acc.w);
    }
    for (; e < n; e++) {
        int s = bp[e];
        float w = node_dinv(s) * di;
        float4 v = h4[s * 32 + lane];
        acc.x = fmaf(v.x, w, acc.x); acc.y = fmaf(v.y, w, acc.y);
        acc.z = fmaf(v.z, w, acc.z); acc.w = fmaf(v.w, w, acc.w);
    }
    return acc;
}

// ---------------- layer-1 aggregation: warp per node, +b1, relu ----------------
__global__ void k_agg1(const float* __restrict__ h, const float* __restrict__ bias,
                       float* __restrict__ out) {
    int node = blockIdx.x * (blockDim.x >> 5) + (threadIdx.x >> 5);
    if (node >= NN) return;
    int lane = threadIdx.x & 31;
    float4 acc = gather_node((const float4*)h, node, lane);
    float4 b = ((const float4*)bias)[lane];
    acc.x = fmaxf(acc.x + b.x, 0.f);
    acc.y = fmaxf(acc.y + b.y, 0.f);
    acc.z = fmaxf(acc.z + b.z, 0.f);
    acc.w = fmaxf(acc.w + b.w, 0.f);
    ((float4*)out)[node * 32 + lane] = acc;
}

// ---------------- layer-2 aggregation fused with (W2@Wc) head + log-softmax ----------------
// m = A h1 per node (warp); logits = m @ Wfused + bfused; log_softmax.
// 256 threads = 8 warps = 8 nodes per block.
__global__ void k_agg2_head(const float* __restrict__ h1, float* __restrict__ out) {
    __shared__ float Wfs[FH * CC];     // 20 KB
    __shared__ float bfs[CC];
    __shared__ float hrow[8][FH];

    int tid = threadIdx.x;
    int lane = tid & 31;
    int w = tid >> 5;
    for (int i = tid; i < FH * CC; i += 256) Wfs[i] = g_wf[i];
    if (tid < CC) bfs[tid] = g_bf[tid];
    __syncthreads();

    int node = blockIdx.x * 8 + w;
    if (node >= NN) return;

    float4 acc = gather_node((const float4*)h1, node, lane);
    *(float4*)&hrow[w][lane * 4] = acc;
    __syncwarp();

    // logits: 2 classes per lane (c0 = lane, c1 = 32 + lane for lane < 8)
    int c0 = lane;
    int c1 = 32 + lane;
    float l0 = bfs[c0];
    float l1 = (c1 < CC) ? bfs[c1] : -1e30f;
    #pragma unroll 8
    for (int k = 0; k < FH; k++) {
        float hv = hrow[w][k];
        l0 = fmaf(hv, Wfs[k * CC + c0], l0);
        if (c1 < CC) l1 = fmaf(hv, Wfs[k * CC + c1], l1);
    }

    // warp-wide log-softmax over 40 values
    float m = fmaxf(l0, l1);
    #pragma unroll
    for (int o = 16; o > 0; o >>= 1)
        m = fmaxf(m, __shfl_xor_sync(0xFFFFFFFFu, m, o));
    float s = __expf(l0 - m) + ((c1 < CC) ? __expf(l1 - m) : 0.0f);
    #pragma unroll
    for (int o = 16; o > 0; o >>= 1)
        s += __shfl_xor_sync(0xFFFFFFFFu, s, o);
    float lse = m + __logf(s);

    out[node * CC + c0] = l0 - lse;
    if (c1 < CC) out[node * CC + c1] = l1 - lse;
}

// ---------------- launch ----------------
extern "C" void kernel_launch(void* const* d_in, const int* in_sizes, int n_in,
                              void* d_out, int out_size) {
    const float* x   = (const float*)d_in[0];
    const void*  ei  = d_in[1];
    const float* W1  = (const float*)d_in[2];
    const float* b1  = (const float*)d_in[3];
    const float* W2  = (const float*)d_in[4];
    const float* b2  = (const float*)d_in[5];
    const float* Wc  = (const float*)d_in[6];
    const float* bc  = (const float*)d_in[7];
    float* out = (float*)d_out;

    float* d_h;  cudaGetSymbolAddress((void**)&d_h,  g_h);
    float* d_ha; cudaGetSymbolAddress((void**)&d_ha, g_ha);

    static cudaStream_t s2 = nullptr;
    static cudaEvent_t evFork = nullptr, evJoin = nullptr;
    if (!s2) {
        cudaStreamCreateWithFlags(&s2, cudaStreamNonBlocking);
        cudaEventCreateWithFlags(&evFork, cudaEventDisableTiming);
        cudaEventCreateWithFlags(&evJoin, cudaEventDisableTiming);
    }

    int gemm_grid = (NN + 63) / 64;
    int agg_grid  = (NN + 7) / 8;

    // fork: GEMM1 (x @ W1) and the W2@Wc fold are independent of edge structure
    cudaEventRecord(evFork, 0);
    cudaStreamWaitEvent(s2, evFork, 0);
    k_fusew<<<10, 512, 0, s2>>>(W2, Wc, b2, bc);
    k_gemm<<<gemm_grid, 256, 0, s2>>>(x, W1, d_h);
    cudaEventRecord(evJoin, s2);

    // bucket build on main stream (concurrent with s2)
    k_init<<<(NN + 255) / 256, 256>>>((const int*)ei);
    k_build<<<(EE + 255) / 256, 256>>>(ei);

    // join before aggregation needs d_h (and g_wf later)
    cudaStreamWaitEvent(0, evJoin, 0);

    // layer 1 aggregate (+b1, relu)
    k_agg1<<<agg_grid, 256>>>(d_h, b1, d_ha);
    // layer 2 aggregate + fused head + log-softmax
    k_agg2_head<<<agg_grid, 256>>>(d_ha, out);
}

// round 5
// speedup vs baseline: 1.4349x; 1.0559x over previous
#include <cuda_runtime.h>
#include <cuda_fp16.h>
#include <math.h>

// Problem constants (fixed shapes)
#define NN 10000
#define EE 640000
#define FH 128          // F_IN == H == 128
#define CC 40
#define BKT 256         // bucket capacity per node (max degree ~110 for this dist)

// ---------------- scratch (device globals; no allocation allowed) ----------------
__device__ __align__(256) int    g_cnt[NN];          // in-degree counts (no self-loop)
__device__ __align__(256) int    g_bkt[NN * BKT];    // padded adjacency buckets (src ids)
__device__ __align__(256) __half g_h[NN * FH];       // GEMM1 output (fp16)
__device__ __align__(256) __half g_ha[NN * FH];      // layer-1 output (fp16, relu'd)
__device__ __align__(256) float  g_wf[FH * CC];      // Wfused = W2 @ Wc
__device__ __align__(256) float  g_bf[CC];           // bfused = b2 @ Wc + bc
__device__ int g_is64;                               // 1 if edge_index is int64

// ---------------- kernel 0: zero counts + detect edge dtype ----------------
__global__ void k_init(const int* __restrict__ w) {
    int i = blockIdx.x * blockDim.x + threadIdx.x;
    if (i < NN) g_cnt[i] = 0;
    if (i == 0) {
        int is64 = 1;
        #pragma unroll
        for (int j = 0; j < 8; j++)
            if (w[2 * j + 1] != 0) is64 = 0;
        g_is64 = is64;
    }
}

__device__ __forceinline__ int load_idx(const void* __restrict__ ei, int is64, long long pos) {
    if (is64) return (int)(((const long long*)ei)[pos]);
    return ((const int*)ei)[pos];
}

// ---------------- kernel 1: single-pass bucket build ----------------
__global__ void k_build(const void* __restrict__ ei) {
    int e = blockIdx.x * blockDim.x + threadIdx.x;
    int is64 = g_is64;
    if (e < EE) {
        int src = load_idx(ei, is64, e);
        int dst = load_idx(ei, is64, (long long)EE + e);
        if ((unsigned)dst < NN && (unsigned)src < NN) {
            int pos = atomicAdd(&g_cnt[dst], 1);
            if (pos < BKT) g_bkt[dst * BKT + pos] = src;
        }
    }
}

// ---------------- kernel: Wfused = W2 @ Wc, bfused = b2 @ Wc + bc ----------------
__global__ void k_fusew(const float* __restrict__ W2, const float* __restrict__ Wc,
                        const float* __restrict__ b2, const float* __restrict__ bc) {
    int idx = blockIdx.x * blockDim.x + threadIdx.x;
    if (idx < FH * CC) {
        int k = idx / CC;
        int c = idx % CC;
        float acc = 0.0f;
        #pragma unroll 8
        for (int j = 0; j < FH; j++)
            acc = fmaf(W2[k * FH + j], Wc[j * CC + c], acc);
        g_wf[idx] = acc;
    }
    if (idx < CC) {
        float acc = bc[idx];
        #pragma unroll 8
        for (int j = 0; j < FH; j++)
            acc = fmaf(b2[j], Wc[j * CC + idx], acc);
        g_bf[idx] = acc;
    }
}

// ---------------- GEMM: C[M,128] = A[M,128] @ W[128,128], fp16 output ----------------
// BM=64, BN=128, BK=32, 256 threads, 4x8 per thread
__global__ void k_gemm(const float* __restrict__ A, const float* __restrict__ W,
                       __half* __restrict__ Cmat) {
    __shared__ float As[64][32];
    __shared__ float Bs[32][128];
    int tid = threadIdx.x;
    int tx = tid & 15;
    int ty = tid >> 4;
    int rowBase = blockIdx.x * 64;

    float acc[4][8];
    #pragma unroll
    for (int j = 0; j < 4; j++)
        #pragma unroll
        for (int i = 0; i < 8; i++) acc[j][i] = 0.0f;

    for (int k0 = 0; k0 < 128; k0 += 32) {
        #pragma unroll
        for (int p = 0; p < 2; p++) {
            int f = tid + p * 256;
            int r = f >> 3, c4 = f & 7;
            int grow = rowBase + r;
            float4 v = make_float4(0.f, 0.f, 0.f, 0.f);
            if (grow < NN)
                v = *(const float4*)&A[grow * 128 + k0 + c4 * 4];
            *(float4*)&As[r][c4 * 4] = v;
        }
        #pragma unroll
        for (int p = 0; p < 4; p++) {
            int f = tid + p * 256;
            int r = f >> 5, c4 = f & 31;
            float4 v = *(const float4*)&W[(k0 + r) * 128 + c4 * 4];
            *(float4*)&Bs[r][c4 * 4] = v;
        }
        __syncthreads();
        #pragma unroll
        for (int kk = 0; kk < 32; kk++) {
            float a[4];
            #pragma unroll
            for (int j = 0; j < 4; j++) a[j] = As[ty * 4 + j][kk];
            float4 b0 = *(float4*)&Bs[kk][tx * 8];
            float4 b1 = *(float4*)&Bs[kk][tx * 8 + 4];
            float b[8] = {b0.x, b0.y, b0.z, b0.w, b1.x, b1.y, b1.z, b1.w};
            #pragma unroll
            for (int j = 0; j < 4; j++)
                #pragma unroll
                for (int i = 0; i < 8; i++)
                    acc[j][i] = fmaf(a[j], b[i], acc[j][i]);
        }
        __syncthreads();
    }

    #pragma unroll
    for (int j = 0; j < 4; j++) {
        int row = rowBase + ty * 4 + j;
        if (row < NN) {
            uint4 o;
            *(__half2*)&o.x = __floats2half2_rn(acc[j][0], acc[j][1]);
            *(__half2*)&o.y = __floats2half2_rn(acc[j][2], acc[j][3]);
            *(__half2*)&o.z = __floats2half2_rn(acc[j][4], acc[j][5]);
            *(__half2*)&o.w = __floats2half2_rn(acc[j][6], acc[j][7]);
            *(uint4*)&Cmat[row * 128 + tx * 8] = o;
        }
    }
}

// ---------------- fp16 gather helpers ----------------
__device__ __forceinline__ float node_dinv(int v) {
    return rsqrtf((float)(g_cnt[v] + 1));
}

__device__ __forceinline__ void fma_row(float4& acc, uint2 v, float w) {
    float2 f0 = __half22float2(*reinterpret_cast<__half2*>(&v.x));
    float2 f1 = __half22float2(*reinterpret_cast<__half2*>(&v.y));
    acc.x = fmaf(f0.x, w, acc.x);
    acc.y = fmaf(f0.y, w, acc.y);
    acc.z = fmaf(f1.x, w, acc.z);
    acc.w = fmaf(f1.y, w, acc.w);
}

// warp gathers node's row + neighbor rows (each row 128 fp16 = 32 x uint2)
__device__ __forceinline__ float4 gather_node16(const uint2* __restrict__ h2,
                                                int node, int lane) {
    float di = node_dinv(node);
    float4 acc = make_float4(0.f, 0.f, 0.f, 0.f);
    fma_row(acc, h2[node * 32 + lane], di * di);          // self-loop

    int n = g_cnt[node];
    if (n > BKT) n = BKT;
    const int* __restrict__ bp = &g_bkt[node * BKT];
    int e = 0;
    for (; e + 4 <= n; e += 4) {
        int s0 = bp[e + 0], s1 = bp[e + 1], s2 = bp[e + 2], s3 = bp[e + 3];
        float w_0 = node_dinv(s0) * di;
        float w_1 = node_dinv(s1) * di;
        float w_2 = node_dinv(s2) * di;
        float w_3 = node_dinv(s3) * di;
        uint2 v0 = h2[s0 * 32 + lane];
        uint2 v1 = h2[s1 * 32 + lane];
        uint2 v2 = h2[s2 * 32 + lane];
        uint2 v3 = h2[s3 * 32 + lane];
        fma_row(acc, v0, w_0);
        fma_row(acc, v1, w_1);
        fma_row(acc, v2, w_2);
        fma_row(acc, v3, w_3);
    }
    for (; e < n; e++) {
        int s = bp[e];
        fma_row(acc, h2[s * 32 + lane], node_dinv(s) * di);
    }
    return acc;
}

// ---------------- layer-1 aggregation: warp per node, +b1, relu, fp16 out ----------------
__global__ void k_agg1(const __half* __restrict__ h, const float* __restrict__ bias,
                       __half* __restrict__ out) {
    int node = blockIdx.x * (blockDim.x >> 5) + (threadIdx.x >> 5);
    if (node >= NN) return;
    int lane = threadIdx.x & 31;
    float4 acc = gather_node16((const uint2*)h, node, lane);
    float4 b = ((const float4*)bias)[lane];
    acc.x = fmaxf(acc.x + b.x, 0.f);
    acc.y = fmaxf(acc.y + b.y, 0.f);
    acc.z = fmaxf(acc.z + b.z, 0.f);
    acc.w = fmaxf(acc.w + b.w, 0.f);
    uint2 o;
    *(__half2*)&o.x = __floats2half2_rn(acc.x, acc.y);
    *(__half2*)&o.y = __floats2half2_rn(acc.z, acc.w);
    ((uint2*)out)[node * 32 + lane] = o;
}

// ---------------- layer-2 aggregation fused with (W2@Wc) head + log-softmax ----------------
// 256 threads = 8 warps = 8 nodes per block.
__global__ void k_agg2_head(const __half* __restrict__ h1, float* __restrict__ out) {
    __shared__ float Wfs[FH * CC];     // 20 KB
    __shared__ float bfs[CC];
    __shared__ float hrow[8][FH];

    int tid = threadIdx.x;
    int lane = tid & 31;
    int w = tid >> 5;
    for (int i = tid; i < FH * CC; i += 256) Wfs[i] = g_wf[i];
    if (tid < CC) bfs[tid] = g_bf[tid];
    __syncthreads();

    int node = blockIdx.x * 8 + w;
    if (node >= NN) return;

    float4 acc = gather_node16((const uint2*)h1, node, lane);
    *(float4*)&hrow[w][lane * 4] = acc;
    __syncwarp();

    // logits: 2 classes per lane
    int c0 = lane;
    int c1 = 32 + lane;
    float l0 = bfs[c0];
    float l1 = (c1 < CC) ? bfs[c1] : -1e30f;
    #pragma unroll 8
    for (int k = 0; k < FH; k++) {
        float hv = hrow[w][k];
        l0 = fmaf(hv, Wfs[k * CC + c0], l0);
        if (c1 < CC) l1 = fmaf(hv, Wfs[k * CC + c1], l1);
    }

    // warp-wide log-softmax over 40 values
    float m = fmaxf(l0, l1);
    #pragma unroll
    for (int o = 16; o > 0; o >>= 1)
        m = fmaxf(m, __shfl_xor_sync(0xFFFFFFFFu, m, o));
    float s = __expf(l0 - m) + ((c1 < CC) ? __expf(l1 - m) : 0.0f);
    #pragma unroll
    for (int o = 16; o > 0; o >>= 1)
        s += __shfl_xor_sync(0xFFFFFFFFu, s, o);
    float lse = m + __logf(s);

    out[node * CC + c0] = l0 - lse;
    if (c1 < CC) out[node * CC + c1] = l1 - lse;
}

// ---------------- launch ----------------
extern "C" void kernel_launch(void* const* d_in, const int* in_sizes, int n_in,
                              void* d_out, int out_size) {
    const float* x   = (const float*)d_in[0];
    const void*  ei  = d_in[1];
    const float* W1  = (const float*)d_in[2];
    const float* b1  = (const float*)d_in[3];
    const float* W2  = (const float*)d_in[4];
    const float* b2  = (const float*)d_in[5];
    const float* Wc  = (const float*)d_in[6];
    const float* bc  = (const float*)d_in[7];
    float* out = (float*)d_out;

    __half* d_h;  cudaGetSymbolAddress((void**)&d_h,  g_h);
    __half* d_ha; cudaGetSymbolAddress((void**)&d_ha, g_ha);

    static cudaStream_t s2 = nullptr;
    static cudaEvent_t evFork = nullptr, evJoin = nullptr;
    if (!s2) {
        cudaStreamCreateWithFlags(&s2, cudaStreamNonBlocking);
        cudaEventCreateWithFlags(&evFork, cudaEventDisableTiming);
        cudaEventCreateWithFlags(&evJoin, cudaEventDisableTiming);
    }

    int gemm_grid = (NN + 63) / 64;
    int agg_grid  = (NN + 7) / 8;

    // fork: GEMM1 (x @ W1) and the W2@Wc fold are independent of edge structure
    cudaEventRecord(evFork, 0);
    cudaStreamWaitEvent(s2, evFork, 0);
    k_fusew<<<10, 512, 0, s2>>>(W2, Wc, b2, bc);
    k_gemm<<<gemm_grid, 256, 0, s2>>>(x, W1, d_h);
    cudaEventRecord(evJoin, s2);

    // bucket build on main stream (concurrent with s2)
    k_init<<<(NN + 255) / 256, 256>>>((const int*)ei);
    k_build<<<(EE + 255) / 256, 256>>>(ei);

    // join before aggregation needs d_h (and g_wf later)
    cudaStreamWaitEvent(0, evJoin, 0);

    // layer 1 aggregate (+b1, relu)
    k_agg1<<<agg_grid, 256>>>(d_h, b1, d_ha);
    // layer 2 aggregate + fused head + log-softmax
    k_agg2_head<<<agg_grid, 256>>>(d_ha, out);
}

// round 6
// speedup vs baseline: 1.6062x; 1.1194x over previous
#include <cuda_runtime.h>
#include <cuda_fp16.h>
#include <math.h>

// Problem constants (fixed shapes)
#define NN 10000
#define EE 640000
#define FH 128          // F_IN == H == 128
#define CC 40
#define BKT 256         // bucket capacity per node (max degree ~110 for this dist)

// ---------------- scratch (device globals; no allocation allowed) ----------------
__device__ __align__(256) int    g_cnt[NN];          // in-degree counts (no self-loop)
__device__ __align__(256) int    g_bkt[NN * BKT];    // padded adjacency buckets (src ids)
__device__ __align__(256) __half g_h[NN * FH];       // GEMM1 output (fp16), scaled in place
__device__ __align__(256) __half g_ha[NN * FH];      // layer-1 output (fp16, relu'd, pre-scaled)
__device__ __align__(256) float  g_wf[FH * CC];      // Wfused = W2 @ Wc
__device__ __align__(256) float  g_bf[CC];           // bfused = b2 @ Wc + bc
__device__ int g_is64;                               // 1 if edge_index is int64

// ---------------- kernel 0: zero counts + detect edge dtype ----------------
__global__ void k_init(const int* __restrict__ w) {
    int i = blockIdx.x * blockDim.x + threadIdx.x;
    if (i < NN) g_cnt[i] = 0;
    if (i == 0) {
        int is64 = 1;
        #pragma unroll
        for (int j = 0; j < 8; j++)
            if (w[2 * j + 1] != 0) is64 = 0;
        g_is64 = is64;
    }
}

__device__ __forceinline__ int load_idx(const void* __restrict__ ei, int is64, long long pos) {
    if (is64) return (int)(((const long long*)ei)[pos]);
    return ((const int*)ei)[pos];
}

// ---------------- kernel 1: bucket build, 4 edges/thread for atomic MLP ----------------
#define EQ (EE / 4)      // 160000
__global__ void k_build(const void* __restrict__ ei) {
    int t = blockIdx.x * blockDim.x + threadIdx.x;
    int is64 = g_is64;
    if (t >= EQ) return;
    #pragma unroll
    for (int k = 0; k < 4; k++) {
        int e = t + k * EQ;
        int src = load_idx(ei, is64, e);
        int dst = load_idx(ei, is64, (long long)EE + e);
        if ((unsigned)dst < NN && (unsigned)src < NN) {
            int pos = atomicAdd(&g_cnt[dst], 1);
            if (pos < BKT) g_bkt[dst * BKT + pos] = src;
        }
    }
}

// ---------------- kernel: Wfused = W2 @ Wc, bfused = b2 @ Wc + bc ----------------
__global__ void k_fusew(const float* __restrict__ W2, const float* __restrict__ Wc,
                        const float* __restrict__ b2, const float* __restrict__ bc) {
    int idx = blockIdx.x * blockDim.x + threadIdx.x;
    if (idx < FH * CC) {
        int k = idx / CC;
        int c = idx % CC;
        float acc = 0.0f;
        #pragma unroll 8
        for (int j = 0; j < FH; j++)
            acc = fmaf(W2[k * FH + j], Wc[j * CC + c], acc);
        g_wf[idx] = acc;
    }
    if (idx < CC) {
        float acc = bc[idx];
        #pragma unroll 8
        for (int j = 0; j < FH; j++)
            acc = fmaf(b2[j], Wc[j * CC + idx], acc);
        g_bf[idx] = acc;
    }
}

// ---------------- GEMM: C[M,128] = A[M,128] @ W[128,128], fp16 output ----------------
__global__ void k_gemm(const float* __restrict__ A, const float* __restrict__ W,
                       __half* __restrict__ Cmat) {
    __shared__ float As[64][32];
    __shared__ float Bs[32][128];
    int tid = threadIdx.x;
    int tx = tid & 15;
    int ty = tid >> 4;
    int rowBase = blockIdx.x * 64;

    float acc[4][8];
    #pragma unroll
    for (int j = 0; j < 4; j++)
        #pragma unroll
        for (int i = 0; i < 8; i++) acc[j][i] = 0.0f;

    for (int k0 = 0; k0 < 128; k0 += 32) {
        #pragma unroll
        for (int p = 0; p < 2; p++) {
            int f = tid + p * 256;
            int r = f >> 3, c4 = f & 7;
            int grow = rowBase + r;
            float4 v = make_float4(0.f, 0.f, 0.f, 0.f);
            if (grow < NN)
                v = *(const float4*)&A[grow * 128 + k0 + c4 * 4];
            *(float4*)&As[r][c4 * 4] = v;
        }
        #pragma unroll
        for (int p = 0; p < 4; p++) {
            int f = tid + p * 256;
            int r = f >> 5, c4 = f & 31;
            float4 v = *(const float4*)&W[(k0 + r) * 128 + c4 * 4];
            *(float4*)&Bs[r][c4 * 4] = v;
        }
        __syncthreads();
        #pragma unroll
        for (int kk = 0; kk < 32; kk++) {
            float a[4];
            #pragma unroll
            for (int j = 0; j < 4; j++) a[j] = As[ty * 4 + j][kk];
            float4 b0 = *(float4*)&Bs[kk][tx * 8];
            float4 b1 = *(float4*)&Bs[kk][tx * 8 + 4];
            float b[8] = {b0.x, b0.y, b0.z, b0.w, b1.x, b1.y, b1.z, b1.w};
            #pragma unroll
            for (int j = 0; j < 4; j++)
                #pragma unroll
                for (int i = 0; i < 8; i++)
                    acc[j][i] = fmaf(a[j], b[i], acc[j][i]);
        }
        __syncthreads();
    }

    #pragma unroll
    for (int j = 0; j < 4; j++) {
        int row = rowBase + ty * 4 + j;
        if (row < NN) {
            uint4 o;
            *(__half2*)&o.x = __floats2half2_rn(acc[j][0], acc[j][1]);
            *(__half2*)&o.y = __floats2half2_rn(acc[j][2], acc[j][3]);
            *(__half2*)&o.z = __floats2half2_rn(acc[j][4], acc[j][5]);
            *(__half2*)&o.w = __floats2half2_rn(acc[j][6], acc[j][7]);
            *(uint4*)&Cmat[row * 128 + tx * 8] = o;
        }
    }
}

// ---------------- kernel: in-place row scaling h' = dinv(row) * h ----------------
// one uint4 (8 halves) per thread; 16 uint4 per row
__global__ void k_scale(__half* __restrict__ h) {
    int i = blockIdx.x * blockDim.x + threadIdx.x;
    if (i >= NN * FH / 8) return;
    int row = i >> 4;
    float d = rsqrtf((float)(g_cnt[row] + 1));
    uint4 v = ((uint4*)h)[i];
    __half2* p = (__half2*)&v;
    #pragma unroll
    for (int k = 0; k < 4; k++) {
        float2 f = __half22float2(p[k]);
        p[k] = __floats2half2_rn(f.x * d, f.y * d);
    }
    ((uint4*)h)[i] = v;
}

// ---------------- gather helpers (pre-scaled rows: pure sum) ----------------
__device__ __forceinline__ void add_row(float4& acc, uint2 v) {
    float2 f0 = __half22float2(*reinterpret_cast<__half2*>(&v.x));
    float2 f1 = __half22float2(*reinterpret_cast<__half2*>(&v.y));
    acc.x += f0.x; acc.y += f0.y; acc.z += f1.x; acc.w += f1.y;
}

// warp sums node's own scaled row + neighbor scaled rows (row = 32 x uint2)
__device__ __forceinline__ float4 gather_sum(const uint2* __restrict__ h2,
                                             int node, int lane, int n) {
    float4 acc = make_float4(0.f, 0.f, 0.f, 0.f);
    add_row(acc, h2[node * 32 + lane]);                    // self (already scaled)
    const int* __restrict__ bp = &g_bkt[node * BKT];
    int e = 0;
    for (; e + 8 <= n; e += 8) {
        int s0 = bp[e + 0], s1 = bp[e + 1], s2 = bp[e + 2], s3 = bp[e + 3];
        int s4 = bp[e + 4], s5 = bp[e + 5], s6 = bp[e + 6], s7 = bp[e + 7];
        uint2 v0 = h2[s0 * 32 + lane];
        uint2 v1 = h2[s1 * 32 + lane];
        uint2 v2 = h2[s2 * 32 + lane];
        uint2 v3 = h2[s3 * 32 + lane];
        uint2 v4 = h2[s4 * 32 + lane];
        uint2 v5 = h2[s5 * 32 + lane];
        uint2 v6 = h2[s6 * 32 + lane];
        uint2 v7 = h2[s7 * 32 + lane];
        add_row(acc, v0); add_row(acc, v1); add_row(acc, v2); add_row(acc, v3);
        add_row(acc, v4); add_row(acc, v5); add_row(acc, v6); add_row(acc, v7);
    }
    for (; e < n; e++)
        add_row(acc, h2[bp[e] * 32 + lane]);
    return acc;
}

// ---------------- layer-1 agg: out' = dinv * relu(dinv*sum + b1)  (pre-scaled out) ----------------
__global__ void k_agg1(const __half* __restrict__ h, const float* __restrict__ bias,
                       __half* __restrict__ out) {
    int node = blockIdx.x * (blockDim.x >> 5) + (threadIdx.x >> 5);
    if (node >= NN) return;
    int lane = threadIdx.x & 31;
    int n = g_cnt[node]; if (n > BKT) n = BKT;
    float di = rsqrtf((float)(n + 1));
    float4 acc = gather_sum((const uint2*)h, node, lane, n);
    float4 b = ((const float4*)bias)[lane];
    acc.x = di * fmaxf(fmaf(acc.x, di, b.x), 0.f);
    acc.y = di * fmaxf(fmaf(acc.y, di, b.y), 0.f);
    acc.z = di * fmaxf(fmaf(acc.z, di, b.z), 0.f);
    acc.w = di * fmaxf(fmaf(acc.w, di, b.w), 0.f);
    uint2 o;
    *(__half2*)&o.x = __floats2half2_rn(acc.x, acc.y);
    *(__half2*)&o.y = __floats2half2_rn(acc.z, acc.w);
    ((uint2*)out)[node * 32 + lane] = o;
}

// ---------------- layer-2 agg fused with (W2@Wc) head + log-softmax ----------------
// m = dinv * sum(scaled rows); logits = m @ Wfused + bfused; log_softmax.
__global__ void k_agg2_head(const __half* __restrict__ h1, float* __restrict__ out) {
    __shared__ float Wfs[FH * CC];     // 20 KB
    __shared__ float bfs[CC];
    __shared__ float hrow[8][FH];

    int tid = threadIdx.x;
    int lane = tid & 31;
    int w = tid >> 5;
    for (int i = tid; i < FH * CC; i += 256) Wfs[i] = g_wf[i];
    if (tid < CC) bfs[tid] = g_bf[tid];
    __syncthreads();

    int node = blockIdx.x * 8 + w;
    if (node >= NN) return;

    int n = g_cnt[node]; if (n > BKT) n = BKT;
    float di = rsqrtf((float)(n + 1));
    float4 acc = gather_sum((const uint2*)h1, node, lane, n);
    acc.x *= di; acc.y *= di; acc.z *= di; acc.w *= di;
    *(float4*)&hrow[w][lane * 4] = acc;
    __syncwarp();

    // logits: 2 classes per lane
    int c0 = lane;
    int c1 = 32 + lane;
    float l0 = bfs[c0];
    float l1 = (c1 < CC) ? bfs[c1] : -1e30f;
    #pragma unroll 8
    for (int k = 0; k < FH; k++) {
        float hv = hrow[w][k];
        l0 = fmaf(hv, Wfs[k * CC + c0], l0);
        if (c1 < CC) l1 = fmaf(hv, Wfs[k * CC + c1], l1);
    }

    // warp-wide log-softmax over 40 values
    float m = fmaxf(l0, l1);
    #pragma unroll
    for (int o = 16; o > 0; o >>= 1)
        m = fmaxf(m, __shfl_xor_sync(0xFFFFFFFFu, m, o));
    float s = __expf(l0 - m) + ((c1 < CC) ? __expf(l1 - m) : 0.0f);
    #pragma unroll
    for (int o = 16; o > 0; o >>= 1)
        s += __shfl_xor_sync(0xFFFFFFFFu, s, o);
    float lse = m + __logf(s);

    out[node * CC + c0] = l0 - lse;
    if (c1 < CC) out[node * CC + c1] = l1 - lse;
}

// ---------------- launch ----------------
extern "C" void kernel_launch(void* const* d_in, const int* in_sizes, int n_in,
                              void* d_out, int out_size) {
    const float* x   = (const float*)d_in[0];
    const void*  ei  = d_in[1];
    const float* W1  = (const float*)d_in[2];
    const float* b1  = (const float*)d_in[3];
    const float* W2  = (const float*)d_in[4];
    const float* b2  = (const float*)d_in[5];
    const float* Wc  = (const float*)d_in[6];
    const float* bc  = (const float*)d_in[7];
    float* out = (float*)d_out;

    __half* d_h;  cudaGetSymbolAddress((void**)&d_h,  g_h);
    __half* d_ha; cudaGetSymbolAddress((void**)&d_ha, g_ha);

    static cudaStream_t s2 = nullptr;
    static cudaEvent_t evFork = nullptr, evJoin = nullptr;
    if (!s2) {
        cudaStreamCreateWithFlags(&s2, cudaStreamNonBlocking);
        cudaEventCreateWithFlags(&evFork, cudaEventDisableTiming);
        cudaEventCreateWithFlags(&evJoin, cudaEventDisableTiming);
    }

    int gemm_grid = (NN + 63) / 64;
    int agg_grid  = (NN + 7) / 8;

    // fork: GEMM1 (x @ W1) and the W2@Wc fold are independent of edge structure
    cudaEventRecord(evFork, 0);
    cudaStreamWaitEvent(s2, evFork, 0);
    k_fusew<<<10, 512, 0, s2>>>(W2, Wc, b2, bc);
    k_gemm<<<gemm_grid, 256, 0, s2>>>(x, W1, d_h);
    cudaEventRecord(evJoin, s2);

    // bucket build on main stream (concurrent with s2)
    k_init<<<(NN + 255) / 256, 256>>>((const int*)ei);
    k_build<<<(EQ + 255) / 256, 256>>>(ei);

    // join: scale needs both counts (build) and h (gemm1)
    cudaStreamWaitEvent(0, evJoin, 0);
    k_scale<<<(NN * FH / 8 + 255) / 256, 256>>>(d_h);

    // layer 1 aggregate (+b1, relu, pre-scale for layer 2)
    k_agg1<<<agg_grid, 256>>>(d_h, b1, d_ha);
    // layer 2 aggregate + fused head + log-softmax
    k_agg2_head<<<agg_grid, 256>>>(d_ha, out);
}

// round 7
// speedup vs baseline: 1.7030x; 1.0603x over previous
#include <cuda_runtime.h>
#include <cuda_fp16.h>
#include <math.h>

// Problem constants (fixed shapes)
#define NN 10000
#define EE 640000
#define FH 128          // F_IN == H == 128
#define CC 40
#define BKT 256         // bucket capacity per node (max degree ~110 for this dist)
#define EQ (EE / 4)     // edges handled 4-per-thread

// ---------------- scratch (device globals; no allocation allowed) ----------------
// g_cnt is zero at process start (BSS) and re-zeroed at the end of k_agg2_head,
// so every kernel_launch execution sees zeroed counts (graph-replay safe).
__device__ __align__(256) int    g_cnt[NN];          // in-degree counts (no self-loop)
__device__ __align__(256) int    g_bkt[NN * BKT];    // padded adjacency buckets (src ids)
__device__ __align__(256) __half g_h[NN * FH];       // GEMM1 output (fp16), scaled in place
__device__ __align__(256) __half g_ha[NN * FH];      // layer-1 output (fp16, relu'd, pre-scaled)
__device__ __align__(256) float  g_wf[FH * CC];      // Wfused = W2 @ Wc
__device__ __align__(256) float  g_bf[CC];           // bfused = b2 @ Wc + bc

// ---------------- kernel: bucket build (4 consecutive edges/thread, vector loads) ----------------
// dtype detected inline: for int64 the high words of the first 8 indices are all
// zero; for int32 random node ids that is essentially impossible. The 8 probe
// loads are lane-uniform & L1-broadcast.
__global__ void k_build(const void* __restrict__ ei) {
    int t = blockIdx.x * blockDim.x + threadIdx.x;
    if (t >= EQ) return;

    const int* __restrict__ w = (const int*)ei;
    bool is64 = true;
    #pragma unroll
    for (int j = 0; j < 8; j++)
        if (w[2 * j + 1] != 0) is64 = false;

    int s[4], d[4];
    if (!is64) {
        int4 sv = ((const int4*)w)[t];
        int4 dv = ((const int4*)w)[EQ + t];     // dst half starts at element EE (EE/4 int4s)
        s[0] = sv.x; s[1] = sv.y; s[2] = sv.z; s[3] = sv.w;
        d[0] = dv.x; d[1] = dv.y; d[2] = dv.z; d[3] = dv.w;
    } else {
        const longlong2* __restrict__ L2s = (const longlong2*)ei;
        longlong2 a0 = L2s[2 * t], a1 = L2s[2 * t + 1];
        longlong2 b0 = L2s[EE / 2 + 2 * t], b1 = L2s[EE / 2 + 2 * t + 1];
        s[0] = (int)a0.x; s[1] = (int)a0.y; s[2] = (int)a1.x; s[3] = (int)a1.y;
        d[0] = (int)b0.x; d[1] = (int)b0.y; d[2] = (int)b1.x; d[3] = (int)b1.y;
    }

    #pragma unroll
    for (int k = 0; k < 4; k++) {
        if ((unsigned)d[k] < NN && (unsigned)s[k] < NN) {
            int pos = atomicAdd(&g_cnt[d[k]], 1);
            if (pos < BKT) g_bkt[d[k] * BKT + pos] = s[k];
        }
    }
}

// ---------------- kernel: Wfused = W2 @ Wc, bfused = b2 @ Wc + bc ----------------
__global__ void k_fusew(const float* __restrict__ W2, const float* __restrict__ Wc,
                        const float* __restrict__ b2, const float* __restrict__ bc) {
    int idx = blockIdx.x * blockDim.x + threadIdx.x;
    if (idx < FH * CC) {
        int k = idx / CC;
        int c = idx % CC;
        float acc = 0.0f;
        #pragma unroll 8
        for (int j = 0; j < FH; j++)
            acc = fmaf(W2[k * FH + j], Wc[j * CC + c], acc);
        g_wf[idx] = acc;
    }
    if (idx < CC) {
        float acc = bc[idx];
        #pragma unroll 8
        for (int j = 0; j < FH; j++)
            acc = fmaf(b2[j], Wc[j * CC + idx], acc);
        g_bf[idx] = acc;
    }
}

// ---------------- GEMM: C[M,128] = A[M,128] @ W[128,128], fp16 output ----------------
__global__ void k_gemm(const float* __restrict__ A, const float* __restrict__ W,
                       __half* __restrict__ Cmat) {
    __shared__ float As[64][32];
    __shared__ float Bs[32][128];
    int tid = threadIdx.x;
    int tx = tid & 15;
    int ty = tid >> 4;
    int rowBase = blockIdx.x * 64;

    float acc[4][8];
    #pragma unroll
    for (int j = 0; j < 4; j++)
        #pragma unroll
        for (int i = 0; i < 8; i++) acc[j][i] = 0.0f;

    for (int k0 = 0; k0 < 128; k0 += 32) {
        #pragma unroll
        for (int p = 0; p < 2; p++) {
            int f = tid + p * 256;
            int r = f >> 3, c4 = f & 7;
            int grow = rowBase + r;
            float4 v = make_float4(0.f, 0.f, 0.f, 0.f);
            if (grow < NN)
                v = *(const float4*)&A[grow * 128 + k0 + c4 * 4];
            *(float4*)&As[r][c4 * 4] = v;
        }
        #pragma unroll
        for (int p = 0; p < 4; p++) {
            int f = tid + p * 256;
            int r = f >> 5, c4 = f & 31;
            float4 v = *(const float4*)&W[(k0 + r) * 128 + c4 * 4];
            *(float4*)&Bs[r][c4 * 4] = v;
        }
        __syncthreads();
        #pragma unroll
        for (int kk = 0; kk < 32; kk++) {
            float a[4];
            #pragma unroll
            for (int j = 0; j < 4; j++) a[j] = As[ty * 4 + j][kk];
            float4 b0 = *(float4*)&Bs[kk][tx * 8];
            float4 b1 = *(float4*)&Bs[kk][tx * 8 + 4];
            float b[8] = {b0.x, b0.y, b0.z, b0.w, b1.x, b1.y, b1.z, b1.w};
            #pragma unroll
            for (int j = 0; j < 4; j++)
                #pragma unroll
                for (int i = 0; i < 8; i++)
                    acc[j][i] = fmaf(a[j], b[i], acc[j][i]);
        }
        __syncthreads();
    }

    #pragma unroll
    for (int j = 0; j < 4; j++) {
        int row = rowBase + ty * 4 + j;
        if (row < NN) {
            uint4 o;
            *(__half2*)&o.x = __floats2half2_rn(acc[j][0], acc[j][1]);
            *(__half2*)&o.y = __floats2half2_rn(acc[j][2], acc[j][3]);
            *(__half2*)&o.z = __floats2half2_rn(acc[j][4], acc[j][5]);
            *(__half2*)&o.w = __floats2half2_rn(acc[j][6], acc[j][7]);
            *(uint4*)&Cmat[row * 128 + tx * 8] = o;
        }
    }
}

// ---------------- kernel: in-place row scaling h' = dinv(row) * h ----------------
__global__ void k_scale(__half* __restrict__ h) {
    int i = blockIdx.x * blockDim.x + threadIdx.x;
    if (i >= NN * FH / 8) return;
    int row = i >> 4;
    float d = rsqrtf((float)(g_cnt[row] + 1));
    uint4 v = ((uint4*)h)[i];
    __half2* p = (__half2*)&v;
    #pragma unroll
    for (int k = 0; k < 4; k++) {
        float2 f = __half22float2(p[k]);
        p[k] = __floats2half2_rn(f.x * d, f.y * d);
    }
    ((uint4*)h)[i] = v;
}

// ---------------- gather helpers (pre-scaled rows: pure sum) ----------------
__device__ __forceinline__ void add_row(float4& acc, uint2 v) {
    float2 f0 = __half22float2(*reinterpret_cast<__half2*>(&v.x));
    float2 f1 = __half22float2(*reinterpret_cast<__half2*>(&v.y));
    acc.x += f0.x; acc.y += f0.y; acc.z += f1.x; acc.w += f1.y;
}

// warp sums node's own scaled row + neighbor scaled rows (row = 32 x uint2)
// 16 outstanding row loads per iteration; indices via lane-uniform int4 loads.
__device__ __forceinline__ float4 gather_sum(const uint2* __restrict__ h2,
                                             int node, int lane, int n) {
    float4 acc = make_float4(0.f, 0.f, 0.f, 0.f);
    add_row(acc, h2[node * 32 + lane]);                    // self (already scaled)
    const int4* __restrict__ bp4 = (const int4*)&g_bkt[node * BKT];
    int e = 0;
    for (; e + 16 <= n; e += 16) {
        int4 i0 = bp4[(e >> 2) + 0];
        int4 i1 = bp4[(e >> 2) + 1];
        int4 i2 = bp4[(e >> 2) + 2];
        int4 i3 = bp4[(e >> 2) + 3];
        uint2 v0 = h2[i0.x * 32 + lane];
        uint2 v1 = h2[i0.y * 32 + lane];
        uint2 v2 = h2[i0.z * 32 + lane];
        uint2 v3 = h2[i0.w * 32 + lane];
        uint2 v4 = h2[i1.x * 32 + lane];
        uint2 v5 = h2[i1.y * 32 + lane];
        uint2 v6 = h2[i1.z * 32 + lane];
        uint2 v7 = h2[i1.w * 32 + lane];
        uint2 v8 = h2[i2.x * 32 + lane];
        uint2 v9 = h2[i2.y * 32 + lane];
        uint2 va = h2[i2.z * 32 + lane];
        uint2 vb = h2[i2.w * 32 + lane];
        uint2 vc = h2[i3.x * 32 + lane];
        uint2 vd = h2[i3.y * 32 + lane];
        uint2 ve = h2[i3.z * 32 + lane];
        uint2 vf = h2[i3.w * 32 + lane];
        add_row(acc, v0); add_row(acc, v1); add_row(acc, v2); add_row(acc, v3);
        add_row(acc, v4); add_row(acc, v5); add_row(acc, v6); add_row(acc, v7);
        add_row(acc, v8); add_row(acc, v9); add_row(acc, va); add_row(acc, vb);
        add_row(acc, vc); add_row(acc, vd); add_row(acc, ve); add_row(acc, vf);
    }
    for (; e + 4 <= n; e += 4) {
        int4 i0 = bp4[e >> 2];
        uint2 v0 = h2[i0.x * 32 + lane];
        uint2 v1 = h2[i0.y * 32 + lane];
        uint2 v2 = h2[i0.z * 32 + lane];
        uint2 v3 = h2[i0.w * 32 + lane];
        add_row(acc, v0); add_row(acc, v1); add_row(acc, v2); add_row(acc, v3);
    }
    const int* __restrict__ bp = &g_bkt[node * BKT];
    for (; e < n; e++)
        add_row(acc, h2[bp[e] * 32 + lane]);
    return acc;
}

// ---------------- layer-1 agg: out' = dinv * relu(dinv*sum + b1)  (pre-scaled out) ----------------
__global__ void __launch_bounds__(256) k_agg1(const __half* __restrict__ h,
                                              const float* __restrict__ bias,
                                              __half* __restrict__ out) {
    int node = blockIdx.x * (blockDim.x >> 5) + (threadIdx.x >> 5);
    if (node >= NN) return;
    int lane = threadIdx.x & 31;
    int n = g_cnt[node]; if (n > BKT) n = BKT;
    float di = rsqrtf((float)(n + 1));
    float4 acc = gather_sum((const uint2*)h, node, lane, n);
    float4 b = ((const float4*)bias)[lane];
    acc.x = di * fmaxf(fmaf(acc.x, di, b.x), 0.f);
    acc.y = di * fmaxf(fmaf(acc.y, di, b.y), 0.f);
    acc.z = di * fmaxf(fmaf(acc.z, di, b.z), 0.f);
    acc.w = di * fmaxf(fmaf(acc.w, di, b.w), 0.f);
    uint2 o;
    *(__half2*)&o.x = __floats2half2_rn(acc.x, acc.y);
    *(__half2*)&o.y = __floats2half2_rn(acc.z, acc.w);
    ((uint2*)out)[node * 32 + lane] = o;
}

// ---------------- layer-2 agg fused with (W2@Wc) head + log-softmax ----------------
__global__ void __launch_bounds__(256) k_agg2_head(const __half* __restrict__ h1,
                                                   float* __restrict__ out) {
    __shared__ float Wfs[FH * CC];     // 20 KB
    __shared__ float bfs[CC];
    __shared__ float hrow[8][FH];

    int tid = threadIdx.x;
    int lane = tid & 31;
    int w = tid >> 5;
    for (int i = tid; i < FH * CC; i += 256) Wfs[i] = g_wf[i];
    if (tid < CC) bfs[tid] = g_bf[tid];
    __syncthreads();

    int node = blockIdx.x * 8 + w;
    if (node >= NN) return;

    int n = g_cnt[node]; if (n > BKT) n = BKT;
    float di = rsqrtf((float)(n + 1));
    float4 acc = gather_sum((const uint2*)h1, node, lane, n);
    acc.x *= di; acc.y *= di; acc.z *= di; acc.w *= di;
    *(float4*)&hrow[w][lane * 4] = acc;
    __syncwarp();

    // reset count for the next graph replay (this warp is the last reader)
    if (lane == 0) g_cnt[node] = 0;

    // logits: 2 classes per lane
    int c0 = lane;
    int c1 = 32 + lane;
    float l0 = bfs[c0];
    float l1 = (c1 < CC) ? bfs[c1] : -1e30f;
    #pragma unroll 8
    for (int k = 0; k < FH; k++) {
        float hv = hrow[w][k];
        l0 = fmaf(hv, Wfs[k * CC + c0], l0);
        if (c1 < CC) l1 = fmaf(hv, Wfs[k * CC + c1], l1);
    }

    // warp-wide log-softmax over 40 values
    float m = fmaxf(l0, l1);
    #pragma unroll
    for (int o = 16; o > 0; o >>= 1)
        m = fmaxf(m, __shfl_xor_sync(0xFFFFFFFFu, m, o));
    float s = __expf(l0 - m) + ((c1 < CC) ? __expf(l1 - m) : 0.0f);
    #pragma unroll
    for (int o = 16; o > 0; o >>= 1)
        s += __shfl_xor_sync(0xFFFFFFFFu, s, o);
    float lse = m + __logf(s);

    out[node * CC + c0] = l0 - lse;
    if (c1 < CC) out[node * CC + c1] = l1 - lse;
}

// ---------------- launch ----------------
extern "C" void kernel_launch(void* const* d_in, const int* in_sizes, int n_in,
                              void* d_out, int out_size) {
    const float* x   = (const float*)d_in[0];
    const void*  ei  = d_in[1];
    const float* W1  = (const float*)d_in[2];
    const float* b1  = (const float*)d_in[3];
    const float* W2  = (const float*)d_in[4];
    const float* b2  = (const float*)d_in[5];
    const float* Wc  = (const float*)d_in[6];
    const float* bc  = (const float*)d_in[7];
    float* out = (float*)d_out;

    __half* d_h;  cudaGetSymbolAddress((void**)&d_h,  g_h);
    __half* d_ha; cudaGetSymbolAddress((void**)&d_ha, g_ha);

    static cudaStream_t s2 = nullptr;
    static cudaEvent_t evFork = nullptr, evJoin = nullptr;
    if (!s2) {
        cudaStreamCreateWithFlags(&s2, cudaStreamNonBlocking);
        cudaEventCreateWithFlags(&evFork, cudaEventDisableTiming);
        cudaEventCreateWithFlags(&evJoin, cudaEventDisableTiming);
    }

    int gemm_grid = (NN + 63) / 64;
    int agg_grid  = (NN + 7) / 8;

    // fork: GEMM1 (x @ W1) and the W2@Wc fold are independent of edge structure
    cudaEventRecord(evFork, 0);
    cudaStreamWaitEvent(s2, evFork, 0);
    k_fusew<<<10, 512, 0, s2>>>(W2, Wc, b2, bc);
    k_gemm<<<gemm_grid, 256, 0, s2>>>(x, W1, d_h);
    cudaEventRecord(evJoin, s2);

    // bucket build on main stream (concurrent with s2); counts arrive zeroed
    k_build<<<(EQ + 255) / 256, 256>>>(ei);

    // join: scale needs both counts (build) and h (gemm1)
    cudaStreamWaitEvent(0, evJoin, 0);
    k_scale<<<(NN * FH / 8 + 255) / 256, 256>>>(d_h);

    // layer 1 aggregate (+b1, relu, pre-scale for layer 2)
    k_agg1<<<agg_grid, 256>>>(d_h, b1, d_ha);
    // layer 2 aggregate + fused head + log-softmax (also re-zeroes counts)
    k_agg2_head<<<agg_grid, 256>>>(d_ha, out);
}

// round 8
// speedup vs baseline: 2.0704x; 1.2157x over previous
#include <cuda_runtime.h>
#include <cuda_fp16.h>
#include <math.h>

// Problem constants (fixed shapes)
#define NN 10000
#define EE 640000
#define FH 128          // F_IN == H == 128
#define CC 40
#define BKT 256         // bucket capacity per node (max degree ~110 for this dist)
#define EQ (EE / 4)     // edges handled 4-per-thread in build
#define GEMM_BLOCKS 157 // ceil(10000/64)
#define FUSE_BLOCKS 20  // 5120 outputs / 256

typedef unsigned long long ull;

// ---------------- scratch (device globals; no allocation allowed) ----------------
// g_cnt is zero at process start (BSS) and re-zeroed at the end of k_agg2_head,
// so every kernel_launch execution sees zeroed counts (graph-replay safe).
// Rows NN of g_h / g_ha are permanent zero rows (never written) used as gather pads.
__device__ __align__(256) int    g_cnt[NN];             // in-degree counts (no self-loop)
__device__ __align__(256) int    g_bkt[NN * BKT];       // padded adjacency buckets (src ids)
__device__ __align__(256) __half g_h[(NN + 1) * FH];    // GEMM1 output (fp16), scaled in place
__device__ __align__(256) __half g_ha[(NN + 1) * FH];   // layer-1 output (fp16, pre-scaled)
__device__ __align__(256) float  g_wf[FH * CC];         // Wfused = W2 @ Wc
__device__ __align__(256) float  g_bf[CC];              // bfused = b2 @ Wc + bc

// ---------------- packed f32x2 helpers (sm_103a) ----------------
__device__ __forceinline__ ull addf2(ull a, ull b) {
    ull r; asm("add.rn.f32x2 %0, %1, %2;" : "=l"(r) : "l"(a), "l"(b)); return r;
}
__device__ __forceinline__ ull h2tof2(unsigned int hv) {
    __half2 h = *reinterpret_cast<__half2*>(&hv);
    float2 f = __half22float2(h);
    ull r; asm("mov.b64 %0, {%1, %2};" : "=l"(r) : "f"(f.x), "f"(f.y)); return r;
}
__device__ __forceinline__ float2 unpackf2(ull a) {
    float2 f; asm("mov.b64 {%0, %1}, %2;" : "=f"(f.x), "=f"(f.y) : "l"(a)); return f;
}

// ---------------- kernel: bucket build (4 consecutive edges/thread, vector loads) ----------------
__global__ void k_build(const void* __restrict__ ei) {
    int t = blockIdx.x * blockDim.x + threadIdx.x;
    if (t >= EQ) return;

    const int* __restrict__ w = (const int*)ei;
    bool is64 = true;
    #pragma unroll
    for (int j = 0; j < 8; j++)
        if (w[2 * j + 1] != 0) is64 = false;

    int s[4], d[4];
    if (!is64) {
        int4 sv = ((const int4*)w)[t];
        int4 dv = ((const int4*)w)[EQ + t];
        s[0] = sv.x; s[1] = sv.y; s[2] = sv.z; s[3] = sv.w;
        d[0] = dv.x; d[1] = dv.y; d[2] = dv.z; d[3] = dv.w;
    } else {
        const longlong2* __restrict__ L2s = (const longlong2*)ei;
        longlong2 a0 = L2s[2 * t], a1 = L2s[2 * t + 1];
        longlong2 b0 = L2s[EE / 2 + 2 * t], b1 = L2s[EE / 2 + 2 * t + 1];
        s[0] = (int)a0.x; s[1] = (int)a0.y; s[2] = (int)a1.x; s[3] = (int)a1.y;
        d[0] = (int)b0.x; d[1] = (int)b0.y; d[2] = (int)b1.x; d[3] = (int)b1.y;
    }

    #pragma unroll
    for (int k = 0; k < 4; k++) {
        if ((unsigned)d[k] < NN && (unsigned)s[k] < NN) {
            int pos = atomicAdd(&g_cnt[d[k]], 1);
            if (pos < BKT - 2) g_bkt[d[k] * BKT + pos] = s[k];
        }
    }
}

// ---------------- GEMM (+ merged W2@Wc fold): C[M,128] = A[M,128] @ W[128,128], fp16 out ----------------
__global__ void k_gemm(const float* __restrict__ A, const float* __restrict__ W,
                       __half* __restrict__ Cmat,
                       const float* __restrict__ W2, const float* __restrict__ Wc,
                       const float* __restrict__ b2, const float* __restrict__ bc) {
    if (blockIdx.x >= GEMM_BLOCKS) {
        // fused-weight fold blocks
        int idx = (blockIdx.x - GEMM_BLOCKS) * 256 + threadIdx.x;
        if (idx < FH * CC) {
            int k = idx / CC, c = idx % CC;
            float acc = 0.0f;
            #pragma unroll 8
            for (int j = 0; j < FH; j++)
                acc = fmaf(W2[k * FH + j], Wc[j * CC + c], acc);
            g_wf[idx] = acc;
        }
        if (idx < CC) {
            float acc = bc[idx];
            #pragma unroll 8
            for (int j = 0; j < FH; j++)
                acc = fmaf(b2[j], Wc[j * CC + idx], acc);
            g_bf[idx] = acc;
        }
        return;
    }

    __shared__ float As[64][32];
    __shared__ float Bs[32][128];
    int tid = threadIdx.x;
    int tx = tid & 15;
    int ty = tid >> 4;
    int rowBase = blockIdx.x * 64;

    float acc[4][8];
    #pragma unroll
    for (int j = 0; j < 4; j++)
        #pragma unroll
        for (int i = 0; i < 8; i++) acc[j][i] = 0.0f;

    for (int k0 = 0; k0 < 128; k0 += 32) {
        #pragma unroll
        for (int p = 0; p < 2; p++) {
            int f = tid + p * 256;
            int r = f >> 3, c4 = f & 7;
            int grow = rowBase + r;
            float4 v = make_float4(0.f, 0.f, 0.f, 0.f);
            if (grow < NN)
                v = *(const float4*)&A[grow * 128 + k0 + c4 * 4];
            *(float4*)&As[r][c4 * 4] = v;
        }
        #pragma unroll
        for (int p = 0; p < 4; p++) {
            int f = tid + p * 256;
            int r = f >> 5, c4 = f & 31;
            float4 v = *(const float4*)&W[(k0 + r) * 128 + c4 * 4];
            *(float4*)&Bs[r][c4 * 4] = v;
        }
        __syncthreads();
        #pragma unroll
        for (int kk = 0; kk < 32; kk++) {
            float a[4];
            #pragma unroll
            for (int j = 0; j < 4; j++) a[j] = As[ty * 4 + j][kk];
            float4 b0 = *(float4*)&Bs[kk][tx * 8];
            float4 b1 = *(float4*)&Bs[kk][tx * 8 + 4];
            float b[8] = {b0.x, b0.y, b0.z, b0.w, b1.x, b1.y, b1.z, b1.w};
            #pragma unroll
            for (int j = 0; j < 4; j++)
                #pragma unroll
                for (int i = 0; i < 8; i++)
                    acc[j][i] = fmaf(a[j], b[i], acc[j][i]);
        }
        __syncthreads();
    }

    #pragma unroll
    for (int j = 0; j < 4; j++) {
        int row = rowBase + ty * 4 + j;
        if (row < NN) {
            uint4 o;
            *(__half2*)&o.x = __floats2half2_rn(acc[j][0], acc[j][1]);
            *(__half2*)&o.y = __floats2half2_rn(acc[j][2], acc[j][3]);
            *(__half2*)&o.z = __floats2half2_rn(acc[j][4], acc[j][5]);
            *(__half2*)&o.w = __floats2half2_rn(acc[j][6], acc[j][7]);
            *(uint4*)&Cmat[row * 128 + tx * 8] = o;
        }
    }
}

// ---------------- kernel: in-place row scaling h' = dinv(row) * h  + bucket self/pad ----------------
__global__ void k_scale(__half* __restrict__ h) {
    int i = blockIdx.x * blockDim.x + threadIdx.x;
    // append self (and zero-row pad if needed) so every bucket list has even length
    if (i < NN) {
        int n = g_cnt[i]; if (n > BKT - 2) n = BKT - 2;
        g_bkt[i * BKT + n] = i;                 // self entry
        if (!(n & 1)) g_bkt[i * BKT + n + 1] = NN;  // pad -> permanent zero row
    }
    if (i >= NN * FH / 8) return;
    int row = i >> 4;
    float d = rsqrtf((float)(g_cnt[row] + 1));
    uint4 v = ((uint4*)h)[i];
    __half2* p = (__half2*)&v;
    #pragma unroll
    for (int k = 0; k < 4; k++) {
        float2 f = __half22float2(p[k]);
        p[k] = __floats2half2_rn(f.x * d, f.y * d);
    }
    ((uint4*)h)[i] = v;
}

// ---------------- paired gather: 2 rows per LDG.128 warp instruction ----------------
// lanes 0-15 handle even list entries, lanes 16-31 odd entries; each lane loads
// 8 halves (16B) of its row. Result: lanes 0-15 hold features [8*lane, 8*lane+8).
__device__ __forceinline__ void gather_paired(const __half* __restrict__ h,
                                              int node, int lane, int m,
                                              float out[8]) {
    int half = lane >> 4;
    int fl = lane & 15;
    const __half* __restrict__ rowoff = h + fl * 8;
    const int4* __restrict__ bp4 = (const int4*)&g_bkt[node * BKT];
    ull a0 = 0, a1 = 0, a2 = 0, a3 = 0;

    int e = 0;
    for (; e + 16 <= m; e += 16) {
        int4 iA = bp4[(e >> 2) + 0];
        int4 iB = bp4[(e >> 2) + 1];
        int4 iC = bp4[(e >> 2) + 2];
        int4 iD = bp4[(e >> 2) + 3];
        int s0 = half ? iA.y : iA.x;
        int s1 = half ? iA.w : iA.z;
        int s2 = half ? iB.y : iB.x;
        int s3 = half ? iB.w : iB.z;
        int s4 = half ? iC.y : iC.x;
        int s5 = half ? iC.w : iC.z;
        int s6 = half ? iD.y : iD.x;
        int s7 = half ? iD.w : iD.z;
        uint4 v0 = *(const uint4*)(rowoff + s0 * FH);
        uint4 v1 = *(const uint4*)(rowoff + s1 * FH);
        uint4 v2 = *(const uint4*)(rowoff + s2 * FH);
        uint4 v3 = *(const uint4*)(rowoff + s3 * FH);
        uint4 v4 = *(const uint4*)(rowoff + s4 * FH);
        uint4 v5 = *(const uint4*)(rowoff + s5 * FH);
        uint4 v6 = *(const uint4*)(rowoff + s6 * FH);
        uint4 v7 = *(const uint4*)(rowoff + s7 * FH);
        a0 = addf2(a0, h2tof2(v0.x)); a1 = addf2(a1, h2tof2(v0.y));
        a2 = addf2(a2, h2tof2(v0.z)); a3 = addf2(a3, h2tof2(v0.w));
        a0 = addf2(a0, h2tof2(v1.x)); a1 = addf2(a1, h2tof2(v1.y));
        a2 = addf2(a2, h2tof2(v1.z)); a3 = addf2(a3, h2tof2(v1.w));
        a0 = addf2(a0, h2tof2(v2.x)); a1 = addf2(a1, h2tof2(v2.y));
        a2 = addf2(a2, h2tof2(v2.z)); a3 = addf2(a3, h2tof2(v2.w));
        a0 = addf2(a0, h2tof2(v3.x)); a1 = addf2(a1, h2tof2(v3.y));
        a2 = addf2(a2, h2tof2(v3.z)); a3 = addf2(a3, h2tof2(v3.w));
        a0 = addf2(a0, h2tof2(v4.x)); a1 = addf2(a1, h2tof2(v4.y));
        a2 = addf2(a2, h2tof2(v4.z)); a3 = addf2(a3, h2tof2(v4.w));
        a0 = addf2(a0, h2tof2(v5.x)); a1 = addf2(a1, h2tof2(v5.y));
        a2 = addf2(a2, h2tof2(v5.z)); a3 = addf2(a3, h2tof2(v5.w));
        a0 = addf2(a0, h2tof2(v6.x)); a1 = addf2(a1, h2tof2(v6.y));
        a2 = addf2(a2, h2tof2(v6.z)); a3 = addf2(a3, h2tof2(v6.w));
        a0 = addf2(a0, h2tof2(v7.x)); a1 = addf2(a1, h2tof2(v7.y));
        a2 = addf2(a2, h2tof2(v7.z)); a3 = addf2(a3, h2tof2(v7.w));
    }
    const int* __restrict__ bp = (const int*)bp4;
    for (; e + 2 <= m; e += 2) {
        int s = bp[e + half];
        uint4 v = *(const uint4*)(rowoff + s * FH);
        a0 = addf2(a0, h2tof2(v.x)); a1 = addf2(a1, h2tof2(v.y));
        a2 = addf2(a2, h2tof2(v.z)); a3 = addf2(a3, h2tof2(v.w));
    }

    // combine halves: lane L (<16) += lane L+16
    float2 f0 = unpackf2(a0), f1 = unpackf2(a1), f2 = unpackf2(a2), f3 = unpackf2(a3);
    out[0] = f0.x + __shfl_down_sync(0xFFFFFFFFu, f0.x, 16);
    out[1] = f0.y + __shfl_down_sync(0xFFFFFFFFu, f0.y, 16);
    out[2] = f1.x + __shfl_down_sync(0xFFFFFFFFu, f1.x, 16);
    out[3] = f1.y + __shfl_down_sync(0xFFFFFFFFu, f1.y, 16);
    out[4] = f2.x + __shfl_down_sync(0xFFFFFFFFu, f2.x, 16);
    out[5] = f2.y + __shfl_down_sync(0xFFFFFFFFu, f2.y, 16);
    out[6] = f3.x + __shfl_down_sync(0xFFFFFFFFu, f3.x, 16);
    out[7] = f3.y + __shfl_down_sync(0xFFFFFFFFu, f3.y, 16);
}

// ---------------- layer-1 agg: out' = dinv * relu(dinv*sum + b1)  (pre-scaled out) ----------------
__global__ void __launch_bounds__(256) k_agg1(const __half* __restrict__ h,
                                              const float* __restrict__ bias,
                                              __half* __restrict__ out) {
    int node = blockIdx.x * 8 + (threadIdx.x >> 5);
    if (node >= NN) return;
    int lane = threadIdx.x & 31;
    int n = g_cnt[node]; if (n > BKT - 2) n = BKT - 2;
    int m = (n + 2) & ~1;
    float di = rsqrtf((float)(n + 1));
    float f[8];
    gather_paired(h, node, lane, m, f);
    if (lane < 16) {
        float4 b0 = *(const float4*)&bias[lane * 8];
        float4 b1 = *(const float4*)&bias[lane * 8 + 4];
        float bb[8] = {b0.x, b0.y, b0.z, b0.w, b1.x, b1.y, b1.z, b1.w};
        float r[8];
        #pragma unroll
        for (int k = 0; k < 8; k++)
            r[k] = di * fmaxf(fmaf(f[k], di, bb[k]), 0.f);
        uint4 o;
        *(__half2*)&o.x = __floats2half2_rn(r[0], r[1]);
        *(__half2*)&o.y = __floats2half2_rn(r[2], r[3]);
        *(__half2*)&o.z = __floats2half2_rn(r[4], r[5]);
        *(__half2*)&o.w = __floats2half2_rn(r[6], r[7]);
        *(uint4*)&out[node * FH + lane * 8] = o;
    }
}

// ---------------- layer-2 agg fused with (W2@Wc) head + log-softmax ----------------
// 512 threads = 16 warps = 16 nodes per block.
__global__ void __launch_bounds__(512) k_agg2_head(const __half* __restrict__ h1,
                                                   float* __restrict__ out) {
    __shared__ float Wfs[FH * CC];     // 20 KB
    __shared__ float bfs[CC];
    __shared__ float hrow[16][FH];     // 8 KB

    int tid = threadIdx.x;
    int lane = tid & 31;
    int w = tid >> 5;
    for (int i = tid; i < FH * CC; i += 512) Wfs[i] = g_wf[i];
    if (tid < CC) bfs[tid] = g_bf[tid];
    __syncthreads();

    int node = blockIdx.x * 16 + w;
    if (node >= NN) return;

    int n = g_cnt[node]; if (n > BKT - 2) n = BKT - 2;
    int m = (n + 2) & ~1;
    float di = rsqrtf((float)(n + 1));
    float f[8];
    gather_paired(h1, node, lane, m, f);
    if (lane < 16) {
        float4 o0 = make_float4(f[0] * di, f[1] * di, f[2] * di, f[3] * di);
        float4 o1 = make_float4(f[4] * di, f[5] * di, f[6] * di, f[7] * di);
        *(float4*)&hrow[w][lane * 8]     = o0;
        *(float4*)&hrow[w][lane * 8 + 4] = o1;
    }
    __syncwarp();

    // reset count for the next graph replay (this warp is the last reader)
    if (lane == 0) g_cnt[node] = 0;

    // logits: 2 classes per lane
    int c0 = lane;
    int c1 = 32 + lane;
    float l0 = bfs[c0];
    float l1 = (c1 < CC) ? bfs[c1] : -1e30f;
    #pragma unroll 8
    for (int k = 0; k < FH; k++) {
        float hv = hrow[w][k];
        l0 = fmaf(hv, Wfs[k * CC + c0], l0);
        if (c1 < CC) l1 = fmaf(hv, Wfs[k * CC + c1], l1);
    }

    // warp-wide log-softmax over 40 values
    float mx = fmaxf(l0, l1);
    #pragma unroll
    for (int o = 16; o > 0; o >>= 1)
        mx = fmaxf(mx, __shfl_xor_sync(0xFFFFFFFFu, mx, o));
    float s = __expf(l0 - mx) + ((c1 < CC) ? __expf(l1 - mx) : 0.0f);
    #pragma unroll
    for (int o = 16; o > 0; o >>= 1)
        s += __shfl_xor_sync(0xFFFFFFFFu, s, o);
    float lse = mx + __logf(s);

    out[node * CC + c0] = l0 - lse;
    if (c1 < CC) out[node * CC + c1] = l1 - lse;
}

// ---------------- launch ----------------
extern "C" void kernel_launch(void* const* d_in, const int* in_sizes, int n_in,
                              void* d_out, int out_size) {
    const float* x   = (const float*)d_in[0];
    const void*  ei  = d_in[1];
    const float* W1  = (const float*)d_in[2];
    const float* b1  = (const float*)d_in[3];
    const float* W2  = (const float*)d_in[4];
    const float* b2  = (const float*)d_in[5];
    const float* Wc  = (const float*)d_in[6];
    const float* bc  = (const float*)d_in[7];
    float* out = (float*)d_out;

    __half* d_h;  cudaGetSymbolAddress((void**)&d_h,  g_h);
    __half* d_ha; cudaGetSymbolAddress((void**)&d_ha, g_ha);

    static cudaStream_t s2 = nullptr;
    static cudaEvent_t evFork = nullptr, evJoin = nullptr;
    if (!s2) {
        cudaStreamCreateWithFlags(&s2, cudaStreamNonBlocking);
        cudaEventCreateWithFlags(&evFork, cudaEventDisableTiming);
        cudaEventCreateWithFlags(&evJoin, cudaEventDisableTiming);
    }

    // fork: GEMM1 (x @ W1, + merged W2@Wc fold) is independent of edge structure
    cudaEventRecord(evFork, 0);
    cudaStreamWaitEvent(s2, evFork, 0);
    k_gemm<<<GEMM_BLOCKS + FUSE_BLOCKS, 256, 0, s2>>>(x, W1, d_h, W2, Wc, b2, bc);
    cudaEventRecord(evJoin, s2);

    // bucket build on main stream (concurrent with s2); counts arrive zeroed
    k_build<<<(EQ + 255) / 256, 256>>>(ei);

    // join: scale needs both counts (build) and h (gemm1)
    cudaStreamWaitEvent(0, evJoin, 0);
    k_scale<<<(NN * FH / 8 + 255) / 256, 256>>>(d_h);

    // layer 1 aggregate (+b1, relu, pre-scale for layer 2)
    k_agg1<<<(NN + 7) / 8, 256>>>(d_h, b1, d_ha);
    // layer 2 aggregate + fused head + log-softmax (also re-zeroes counts)
    k_agg2_head<<<(NN + 15) / 16, 512>>>(d_ha, out);
}